// round 10
// baseline (speedup 1.0000x reference)
#include <cuda_runtime.h>
#include <math.h>

#define NN 100000
#define NE 1600000
#define DF 128
#define RR 7
#define NBATCH 4096
#define KAGG ((RR + 1) * DF)   // 1024

// ---------------- persistent scratch (device globals; no allocs) -------------
static __device__ float g_h[2][(size_t)NN * DF];        // ping-pong features
static __device__ float g_agg[(size_t)NN * KAGG];       // [N,1024] = [h | agg_r]
static __device__ int   g_packed[NE];                   // (type<<20)|src, CSR order
static __device__ int   g_rowptr[NN + 1];
static __device__ int   g_fill[NN];
static __device__ int   g_deg[NN];
static __device__ int   g_cnt[NN * RR];
static __device__ float g_invc[NN * RR];
static __device__ float g_W[3 * KAGG * DF];             // fused [root_w; rel_w] per layer (tf32)
static __device__ float g_scale[3 * DF];                // BN scale folded
static __device__ float g_shift[3 * DF];                // BN shift + conv bias folded
static __device__ float g_W0T[256 * 256];               // fc0_w^T (tf32)
static __device__ float g_W1T[256 * 128];               // fc1_w^T (tf32)
static __device__ float g_G[NBATCH * 256];
static __device__ float g_G1[NBATCH * 256];
static __device__ float g_G2[NBATCH * 128];

// ---------------- helpers ----------------------------------------------------
__device__ __forceinline__ float rna(float x) {
    unsigned u;
    asm("cvt.rna.tf32.f32 %0, %1;" : "=r"(u) : "f"(x));
    return __uint_as_float(u);
}
__device__ __forceinline__ float4 rna4(float4 v) {
    v.x = rna(v.x); v.y = rna(v.y); v.z = rna(v.z); v.w = rna(v.w);
    return v;
}

__device__ __forceinline__ void mma_tf32(float* c, const unsigned* a, const unsigned* b) {
    asm volatile(
        "mma.sync.aligned.m16n8k8.row.col.f32.tf32.tf32.f32 "
        "{%0,%1,%2,%3},{%4,%5,%6,%7},{%8,%9},{%0,%1,%2,%3};"
        : "+f"(c[0]), "+f"(c[1]), "+f"(c[2]), "+f"(c[3])
        : "r"(a[0]), "r"(a[1]), "r"(a[2]), "r"(a[3]), "r"(b[0]), "r"(b[1]));
}

// ---------------- graph build ------------------------------------------------
__global__ void k_zero() {
    int i = blockIdx.x * blockDim.x + threadIdx.x;
    if (i < NN * RR) g_cnt[i] = 0;
    if (i < NN) g_deg[i] = 0;
}

__global__ void k_hist(const int* __restrict__ ei, const int* __restrict__ et) {
    int e = blockIdx.x * blockDim.x + threadIdx.x;
    if (e >= NE) return;
    int dst = ei[NE + e];
    int t = et[e];
    atomicAdd(&g_cnt[dst * RR + t], 1);
    atomicAdd(&g_deg[dst], 1);
}

__global__ void k_scan() {  // single-block exclusive scan of g_deg -> g_rowptr/g_fill
    __shared__ int sw[32];
    __shared__ int carry;
    int tid = threadIdx.x, lane = tid & 31, w = tid >> 5;
    if (tid == 0) carry = 0;
    __syncthreads();
    for (int base = 0; base < NN; base += 1024) {
        int i = base + tid;
        int v = (i < NN) ? g_deg[i] : 0;
        int xx = v;
#pragma unroll
        for (int off = 1; off < 32; off <<= 1) {
            int t2 = __shfl_up_sync(0xffffffffu, xx, off);
            if (lane >= off) xx += t2;
        }
        if (lane == 31) sw[w] = xx;
        __syncthreads();
        if (w == 0) {
            int y = sw[lane];
#pragma unroll
            for (int off = 1; off < 32; off <<= 1) {
                int t2 = __shfl_up_sync(0xffffffffu, y, off);
                if (lane >= off) y += t2;
            }
            sw[lane] = y;
        }
        __syncthreads();
        int woff = (w > 0) ? sw[w - 1] : 0;
        int incl = xx + woff;
        int cur = carry;
        if (i < NN) {
            int ex = cur + incl - v;
            g_rowptr[i] = ex;
            g_fill[i] = ex;
        }
        __syncthreads();
        if (tid == 1023) carry = cur + sw[31];
        __syncthreads();
    }
    if (threadIdx.x == 0) g_rowptr[NN] = carry;
}

__global__ void k_invc() {
    int i = blockIdx.x * blockDim.x + threadIdx.x;
    if (i >= NN * RR) return;
    int c = g_cnt[i];
    g_invc[i] = 1.0f / (float)(c > 1 ? c : 1);
}

__global__ void k_scatter(const int* __restrict__ ei, const int* __restrict__ et) {
    int e = blockIdx.x * blockDim.x + threadIdx.x;
    if (e >= NE) return;
    int src = ei[e];
    int dst = ei[NE + e];
    int t = et[e];
    int pos = atomicAdd(&g_fill[dst], 1);
    g_packed[pos] = (t << 20) | src;
}

// ---------------- parameter prep ---------------------------------------------
__global__ void k_prep_w(const float* __restrict__ rel_w, const float* __restrict__ root_w) {
    int tid = blockIdx.x * blockDim.x + threadIdx.x;
    if (tid >= 3 * KAGG * DF) return;
    int l = tid / (KAGG * DF);
    int rem = tid % (KAGG * DF);
    int k = rem / DF;
    int o = rem % DF;
    float v;
    if (k < DF) {
        v = root_w[((size_t)l * DF + k) * DF + o];
    } else {
        int r = (k - DF) >> 7;
        int i = (k - DF) & 127;
        v = rel_w[(((size_t)l * RR + r) * DF + i) * DF + o];
    }
    g_W[tid] = rna(v);
}

__global__ void k_prep_bn(const float* __restrict__ conv_b, const float* __restrict__ bn_g,
                          const float* __restrict__ bn_b, const float* __restrict__ bn_m,
                          const float* __restrict__ bn_v) {
    int tid = blockIdx.x * blockDim.x + threadIdx.x;
    if (tid >= 3 * DF) return;
    int l = tid / DF, d = tid % DF;
    if (l < 2) {
        float s = bn_g[l * DF + d] * rsqrtf(bn_v[l * DF + d] + 1e-5f);
        g_scale[tid] = s;
        g_shift[tid] = (conv_b[l * DF + d] - bn_m[l * DF + d]) * s + bn_b[l * DF + d];
    } else {
        g_scale[tid] = 1.0f;
        g_shift[tid] = conv_b[2 * DF + d];
    }
}

__global__ void k_prep_fc(const float* __restrict__ fc0w, const float* __restrict__ fc1w) {
    int tid = blockIdx.x * blockDim.x + threadIdx.x;
    if (tid < 256 * 256) {
        int o = tid / 256, k = tid % 256;
        g_W0T[k * 256 + o] = rna(fc0w[tid]);
    } else if (tid < 256 * 256 + 128 * 256) {
        int t2 = tid - 256 * 256;
        int o = t2 / 256, k = t2 % 256;
        g_W1T[k * 128 + o] = rna(fc1w[t2]);
    }
}

__global__ void k_embed(const int* __restrict__ x, const float* __restrict__ emb) {
    int tid = blockIdx.x * blockDim.x + threadIdx.x;
    if (tid >= NN * 32) return;
    int n = tid >> 5, j = tid & 31;
    const float4* e4 = (const float4*)emb;
    ((float4*)g_h[0])[(size_t)n * 32 + j] = e4[(size_t)x[n] * 32 + j];
}

// ---------------- CSR pull: per-dst mean aggregation -> AGG row ---------------
__global__ void k_pull(const float* __restrict__ h) {
    int node = (blockIdx.x * blockDim.x + threadIdx.x) >> 5;
    int lane = threadIdx.x & 31;
    if (node >= NN) return;
    int beg = g_rowptr[node];
    int end = g_rowptr[node + 1];
    const float4* h4 = (const float4*)h;

    float4 z = make_float4(0.f, 0.f, 0.f, 0.f);
    float4 a0 = z, a1 = z, a2 = z, a3 = z, a4 = z, a5 = z, a6 = z;

    for (int e = beg; e < end; ++e) {
        int p = g_packed[e];
        int src = p & 0xFFFFF;
        int t = p >> 20;
        float4 v = h4[(size_t)src * 32 + lane];
        switch (t) {
            case 0: a0.x += v.x; a0.y += v.y; a0.z += v.z; a0.w += v.w; break;
            case 1: a1.x += v.x; a1.y += v.y; a1.z += v.z; a1.w += v.w; break;
            case 2: a2.x += v.x; a2.y += v.y; a2.z += v.z; a2.w += v.w; break;
            case 3: a3.x += v.x; a3.y += v.y; a3.z += v.z; a3.w += v.w; break;
            case 4: a4.x += v.x; a4.y += v.y; a4.z += v.z; a4.w += v.w; break;
            case 5: a5.x += v.x; a5.y += v.y; a5.z += v.z; a5.w += v.w; break;
            default: a6.x += v.x; a6.y += v.y; a6.z += v.z; a6.w += v.w; break;
        }
    }

    float4* rowq = (float4*)(g_agg + (size_t)node * KAGG);
    rowq[lane] = rna4(h4[(size_t)node * 32 + lane]);  // root copy
    const float* icp = g_invc + node * RR;
#define ST_REL(ix, av)                                              \
    {                                                               \
        float ic = icp[ix];                                         \
        av.x *= ic; av.y *= ic; av.z *= ic; av.w *= ic;             \
        rowq[32 + (ix)*32 + lane] = rna4(av);                       \
    }
    ST_REL(0, a0) ST_REL(1, a1) ST_REL(2, a2) ST_REL(3, a3)
    ST_REL(4, a4) ST_REL(5, a5) ST_REL(6, a6)
#undef ST_REL
}

// ---------------- generic tf32 GEMM: C[M,Nt] = A[M,K] @ B[K,Nt], fused epilogue
// blockDim 256 (8 warps), CTA tile 128x128, warp tile 32x64, BK=32
__global__ void k_gemm(const float* __restrict__ A, const float* __restrict__ B,
                       const float* __restrict__ scale, const float* __restrict__ shift,
                       float* __restrict__ C, int M, int K, int Nt, int relu, int rnd) {
    __shared__ __align__(16) float As[128 * 36];
    __shared__ __align__(16) float Bs[32 * 132];

    int tid = threadIdx.x;
    int wid = tid >> 5;
    int lane = tid & 31;
    int wm = wid & 3;        // 0..3 (M)
    int wn = wid >> 2;       // 0..1 (N)
    int g = lane >> 2;       // group 0..7
    int tg = lane & 3;       // thread-in-group 0..3

    int bm = blockIdx.x * 128;
    int nb = blockIdx.y * 128;

    float acc[2][8][4];
#pragma unroll
    for (int i = 0; i < 2; i++)
#pragma unroll
        for (int j = 0; j < 8; j++)
#pragma unroll
            for (int k = 0; k < 4; k++) acc[i][j][k] = 0.f;

    for (int kt = 0; kt < K; kt += 32) {
        // load A tile 128x32
#pragma unroll
        for (int i = 0; i < 4; i++) {
            int id = tid + i * 256;
            int row = id >> 3, c4 = id & 7;
            int gr = bm + row;
            float4 v = make_float4(0.f, 0.f, 0.f, 0.f);
            if (gr < M) v = *(const float4*)(A + (size_t)gr * K + kt + c4 * 4);
            *(float4*)(As + row * 36 + c4 * 4) = v;
        }
        // load B tile 32x128
#pragma unroll
        for (int i = 0; i < 4; i++) {
            int id = tid + i * 256;
            int row = id >> 5, c4 = id & 31;
            float4 v = *(const float4*)(B + (size_t)(kt + row) * Nt + nb + c4 * 4);
            *(float4*)(Bs + row * 132 + c4 * 4) = v;
        }
        __syncthreads();

#pragma unroll
        for (int ks = 0; ks < 4; ks++) {
            int kk = ks * 8;
            unsigned a[2][4], b[8][2];
#pragma unroll
            for (int fm = 0; fm < 2; fm++) {
                int r0 = wm * 32 + fm * 16 + g;
                a[fm][0] = __float_as_uint(As[r0 * 36 + kk + tg]);
                a[fm][1] = __float_as_uint(As[(r0 + 8) * 36 + kk + tg]);
                a[fm][2] = __float_as_uint(As[r0 * 36 + kk + tg + 4]);
                a[fm][3] = __float_as_uint(As[(r0 + 8) * 36 + kk + tg + 4]);
            }
#pragma unroll
            for (int fn = 0; fn < 8; fn++) {
                int c0 = wn * 64 + fn * 8 + g;
                b[fn][0] = __float_as_uint(Bs[(kk + tg) * 132 + c0]);
                b[fn][1] = __float_as_uint(Bs[(kk + tg + 4) * 132 + c0]);
            }
#pragma unroll
            for (int fm = 0; fm < 2; fm++)
#pragma unroll
                for (int fn = 0; fn < 8; fn++) mma_tf32(acc[fm][fn], a[fm], b[fn]);
        }
        __syncthreads();
    }

    // epilogue
#pragma unroll
    for (int fm = 0; fm < 2; fm++) {
#pragma unroll
        for (int fn = 0; fn < 8; fn++) {
            int row = bm + wm * 32 + fm * 16 + g;
            int col = nb + wn * 64 + fn * 8 + tg * 2;
#pragma unroll
            for (int p = 0; p < 4; p++) {
                int r = row + (p >> 1) * 8;
                int c = col + (p & 1);
                if (r < M) {
                    float v = acc[fm][fn][p];
                    float s = scale ? scale[c] : 1.0f;
                    v = v * s + shift[c];
                    if (relu) v = fmaxf(v, 0.f);
                    if (rnd) v = rna(v);
                    C[(size_t)r * Nt + c] = v;
                }
            }
        }
    }
}

// ---------------- head --------------------------------------------------------
__global__ void k_gather(const float* __restrict__ h, const int* __restrict__ home,
                         const int* __restrict__ away) {
    int b = (blockIdx.x * blockDim.x + threadIdx.x) >> 5;
    int lane = threadIdx.x & 31;
    if (b >= NBATCH) return;
    const float4* h4 = (const float4*)h;
    float4 hv = h4[(size_t)home[b] * 32 + lane];
    float4 av = h4[(size_t)away[b] * 32 + lane];
    float4* G4 = (float4*)g_G;
    G4[(size_t)b * 64 + lane] = rna4(hv);
    G4[(size_t)b * 64 + 32 + lane] = rna4(av);
}

__global__ void k_head(const float* __restrict__ fc2w, const float* __restrict__ fc2b,
                       float* __restrict__ out) {
    int b = (blockIdx.x * blockDim.x + threadIdx.x) >> 5;
    int lane = threadIdx.x & 31;
    if (b >= NBATCH) return;
    const float4* g4 = (const float4*)g_G2;
    float4 v = g4[(size_t)b * 32 + lane];
    const float4* w4 = (const float4*)fc2w;
    float l[3];
#pragma unroll
    for (int c = 0; c < 3; c++) {
        float4 w = w4[c * 32 + lane];
        float d = v.x * w.x + v.y * w.y + v.z * w.z + v.w * w.w;
#pragma unroll
        for (int off = 16; off; off >>= 1) d += __shfl_xor_sync(0xffffffffu, d, off);
        l[c] = d + fc2b[c];
    }
    float m = fmaxf(l[0], fmaxf(l[1], l[2]));
    float s = expf(l[0] - m) + expf(l[1] - m) + expf(l[2] - m);
    float ls = m + logf(s);
    if (lane < 3) out[b * 3 + lane] = l[lane] - ls;
}

// ---------------- driver --------------------------------------------------------
extern "C" void kernel_launch(void* const* d_in, const int* in_sizes, int n_in,
                              void* d_out, int out_size) {
    const int* x = (const int*)d_in[0];
    const int* ei = (const int*)d_in[1];
    const int* et = (const int*)d_in[2];
    const int* home = (const int*)d_in[3];
    const int* away = (const int*)d_in[4];
    const float* embed = (const float*)d_in[5];
    const float* rel_w = (const float*)d_in[6];
    const float* root_w = (const float*)d_in[7];
    const float* conv_b = (const float*)d_in[8];
    const float* bn_g = (const float*)d_in[9];
    const float* bn_b = (const float*)d_in[10];
    const float* bn_m = (const float*)d_in[11];
    const float* bn_v = (const float*)d_in[12];
    const float* fc0w = (const float*)d_in[13];
    const float* fc0b = (const float*)d_in[14];
    const float* fc1w = (const float*)d_in[15];
    const float* fc1b = (const float*)d_in[16];
    const float* fc2w = (const float*)d_in[17];
    const float* fc2b = (const float*)d_in[18];
    float* out = (float*)d_out;

    float *p_h, *p_agg, *p_W, *p_scale, *p_shift, *p_W0T, *p_W1T, *p_G, *p_G1, *p_G2;
    cudaGetSymbolAddress((void**)&p_h, g_h);
    cudaGetSymbolAddress((void**)&p_agg, g_agg);
    cudaGetSymbolAddress((void**)&p_W, g_W);
    cudaGetSymbolAddress((void**)&p_scale, g_scale);
    cudaGetSymbolAddress((void**)&p_shift, g_shift);
    cudaGetSymbolAddress((void**)&p_W0T, g_W0T);
    cudaGetSymbolAddress((void**)&p_W1T, g_W1T);
    cudaGetSymbolAddress((void**)&p_G, g_G);
    cudaGetSymbolAddress((void**)&p_G1, g_G1);
    cudaGetSymbolAddress((void**)&p_G2, g_G2);

    // graph build (deterministic, redone each launch)
    k_zero<<<(NN * RR + 255) / 256, 256>>>();
    k_hist<<<(NE + 255) / 256, 256>>>(ei, et);
    k_scan<<<1, 1024>>>();
    k_invc<<<(NN * RR + 255) / 256, 256>>>();
    k_scatter<<<(NE + 255) / 256, 256>>>(ei, et);

    // parameter prep
    k_prep_w<<<(3 * KAGG * DF + 255) / 256, 256>>>(rel_w, root_w);
    k_prep_bn<<<2, 256>>>(conv_b, bn_g, bn_b, bn_m, bn_v);
    k_prep_fc<<<(256 * 256 + 128 * 256 + 255) / 256, 256>>>(fc0w, fc1w);
    k_embed<<<(NN * 32 + 255) / 256, 256>>>(x, embed);

    // 3 RGCN layers
    float* hcur = p_h;
    float* hnxt = p_h + (size_t)NN * DF;
    for (int l = 0; l < 3; l++) {
        k_pull<<<(NN + 7) / 8, 256>>>(hcur);
        k_gemm<<<dim3((NN + 127) / 128, 1), 256>>>(
            p_agg, p_W + (size_t)l * KAGG * DF, p_scale + l * DF, p_shift + l * DF,
            hnxt, NN, KAGG, DF, (l < 2) ? 1 : 0, 0);
        float* tmp = hcur; hcur = hnxt; hnxt = tmp;
    }

    // head MLP
    k_gather<<<(NBATCH * 32 + 255) / 256, 256>>>(hcur, home, away);
    k_gemm<<<dim3(NBATCH / 128, 2), 256>>>(p_G, p_W0T, nullptr, fc0b, p_G1,
                                           NBATCH, 256, 256, 1, 1);
    k_gemm<<<dim3(NBATCH / 128, 1), 256>>>(p_G1, p_W1T, nullptr, fc1b, p_G2,
                                           NBATCH, 256, 128, 1, 1);
    k_head<<<(NBATCH * 32 + 255) / 256, 256>>>(fc2w, fc2b, out);
}

// round 12
// speedup vs baseline: 1.2325x; 1.2325x over previous
#include <cuda_runtime.h>
#include <cuda_bf16.h>
#include <stdint.h>
#include <math.h>

#define NN 100000
#define NE 1600000
#define DF 128
#define RR 7
#define NBATCH 4096
#define KAGG ((RR + 1) * DF)   // 1024
#define NBLK ((NN + 255) / 256) // 391

typedef __nv_bfloat16 bf16;
typedef __nv_bfloat162 bf162;

// ---------------- persistent scratch (device globals; no allocs) -------------
static __device__ bf16  g_hb[2][(size_t)NN * DF];       // ping-pong features (bf16)
static __device__ bf16  g_agg[(size_t)NN * KAGG];       // [N,1024] = [h | agg_r] bf16
static __device__ int   g_packed[NE];                   // (type<<20)|src, CSR order
static __device__ int   g_rowptr[NN + 1];
static __device__ int   g_fill[NN];
static __device__ int   g_deg[NN];
static __device__ int   g_cnt[NN * RR];
static __device__ float g_invc[NN * RR];
static __device__ int   g_blocksum[512];
static __device__ bf16  g_W[3 * KAGG * DF];             // fused weights, [l][o][k] bf16
static __device__ float g_scale[3 * DF];                // BN scale folded
static __device__ float g_shift[3 * DF];                // BN shift + conv bias folded
static __device__ bf16  g_W0[256 * 256];                // fc0_w [out][in] bf16
static __device__ bf16  g_W1[128 * 256];                // fc1_w [out][in] bf16
static __device__ bf16  g_G [NBATCH * 256];
static __device__ bf16  g_G1[NBATCH * 256];
static __device__ bf16  g_G2[NBATCH * 128];

// ---------------- helpers ----------------------------------------------------
__device__ __forceinline__ void mma_bf16(float* c, const unsigned* a, const unsigned* b) {
    asm volatile(
        "mma.sync.aligned.m16n8k16.row.col.f32.bf16.bf16.f32 "
        "{%0,%1,%2,%3},{%4,%5,%6,%7},{%8,%9},{%0,%1,%2,%3};"
        : "+f"(c[0]), "+f"(c[1]), "+f"(c[2]), "+f"(c[3])
        : "r"(a[0]), "r"(a[1]), "r"(a[2]), "r"(a[3]), "r"(b[0]), "r"(b[1]));
}
__device__ __forceinline__ void ldm_x4(unsigned* r, uint32_t addr) {
    asm volatile("ldmatrix.sync.aligned.m8n8.x4.shared.b16 {%0,%1,%2,%3},[%4];"
                 : "=r"(r[0]), "=r"(r[1]), "=r"(r[2]), "=r"(r[3]) : "r"(addr));
}

// ---------------- graph build ------------------------------------------------
__global__ void k_zero() {
    int i = blockIdx.x * blockDim.x + threadIdx.x;
    if (i < NN * RR) g_cnt[i] = 0;
}

__global__ void k_hist(const int* __restrict__ ei, const int* __restrict__ et) {
    int e = blockIdx.x * blockDim.x + threadIdx.x;
    if (e >= NE) return;
    atomicAdd(&g_cnt[ei[NE + e] * RR + et[e]], 1);
}

// per-node degree + invc + per-block degree sums
__global__ void k_scanA() {
    int tid = threadIdx.x, lane = tid & 31, w = tid >> 5;
    int i = blockIdx.x * 256 + tid;
    int deg = 0;
    if (i < NN) {
#pragma unroll
        for (int r = 0; r < RR; r++) {
            int c = g_cnt[i * RR + r];
            deg += c;
            g_invc[i * RR + r] = 1.0f / (float)(c > 1 ? c : 1);
        }
        g_deg[i] = deg;
    }
    __shared__ int sw[8];
    int v = deg;
#pragma unroll
    for (int off = 16; off; off >>= 1) v += __shfl_xor_sync(~0u, v, off);
    if (lane == 0) sw[w] = v;
    __syncthreads();
    if (tid == 0) {
        int s = 0;
#pragma unroll
        for (int k = 0; k < 8; k++) s += sw[k];
        g_blocksum[blockIdx.x] = s;
    }
}

// scan 391 block sums (1 block, 512 threads)
__global__ void k_scanB() {
    __shared__ int sw[16];
    int tid = threadIdx.x, lane = tid & 31, w = tid >> 5;
    int v = (tid < NBLK) ? g_blocksum[tid] : 0;
    int x = v;
#pragma unroll
    for (int off = 1; off < 32; off <<= 1) {
        int t = __shfl_up_sync(~0u, x, off);
        if (lane >= off) x += t;
    }
    if (lane == 31) sw[w] = x;
    __syncthreads();
    if (w == 0) {
        int y = (lane < 16) ? sw[lane] : 0;
#pragma unroll
        for (int off = 1; off < 16; off <<= 1) {
            int t = __shfl_up_sync(~0u, y, off);
            if (lane >= off) y += t;
        }
        if (lane < 16) sw[lane] = y;
    }
    __syncthreads();
    int woff = (w > 0) ? sw[w - 1] : 0;
    int excl = woff + x - v;
    if (tid < NBLK) g_blocksum[tid] = excl;
    if (tid == NBLK - 1) g_rowptr[NN] = excl + v;
}

// final rowptr/fill
__global__ void k_scanC() {
    int tid = threadIdx.x, lane = tid & 31, w = tid >> 5;
    int i = blockIdx.x * 256 + tid;
    int v = (i < NN) ? g_deg[i] : 0;
    int x = v;
#pragma unroll
    for (int off = 1; off < 32; off <<= 1) {
        int t = __shfl_up_sync(~0u, x, off);
        if (lane >= off) x += t;
    }
    __shared__ int sw[8];
    if (lane == 31) sw[w] = x;
    __syncthreads();
    int woff = 0;
    for (int k = 0; k < w; k++) woff += sw[k];
    int excl = g_blocksum[blockIdx.x] + woff + x - v;
    if (i < NN) { g_rowptr[i] = excl; g_fill[i] = excl; }
}

__global__ void k_scatter(const int* __restrict__ ei, const int* __restrict__ et) {
    int e = blockIdx.x * blockDim.x + threadIdx.x;
    if (e >= NE) return;
    int src = ei[e];
    int dst = ei[NE + e];
    int t = et[e];
    int pos = atomicAdd(&g_fill[dst], 1);
    g_packed[pos] = (t << 20) | src;
}

// ---------------- parameter prep ---------------------------------------------
// g_W layout: [l][o(128)][k(1024)], k<128 -> root_w[l][k][o], else rel_w[l][r][i][o]
__global__ void k_prep_w(const float* __restrict__ rel_w, const float* __restrict__ root_w) {
    int tid = blockIdx.x * blockDim.x + threadIdx.x;
    if (tid >= 3 * KAGG * DF) return;
    int l = tid / (KAGG * DF);
    int rem = tid % (KAGG * DF);
    int o = rem / KAGG;
    int k = rem % KAGG;
    float v;
    if (k < DF) {
        v = root_w[((size_t)l * DF + k) * DF + o];
    } else {
        int r = (k - DF) >> 7;
        int i = (k - DF) & 127;
        v = rel_w[(((size_t)l * RR + r) * DF + i) * DF + o];
    }
    g_W[tid] = __float2bfloat16(v);
}

__global__ void k_prep_bn(const float* __restrict__ conv_b, const float* __restrict__ bn_g,
                          const float* __restrict__ bn_b, const float* __restrict__ bn_m,
                          const float* __restrict__ bn_v) {
    int tid = blockIdx.x * blockDim.x + threadIdx.x;
    if (tid >= 3 * DF) return;
    int l = tid / DF, d = tid % DF;
    if (l < 2) {
        float s = bn_g[l * DF + d] * rsqrtf(bn_v[l * DF + d] + 1e-5f);
        g_scale[tid] = s;
        g_shift[tid] = (conv_b[l * DF + d] - bn_m[l * DF + d]) * s + bn_b[l * DF + d];
    } else {
        g_scale[tid] = 1.0f;
        g_shift[tid] = conv_b[2 * DF + d];
    }
}

__global__ void k_prep_fc(const float* __restrict__ fc0w, const float* __restrict__ fc1w) {
    int tid = blockIdx.x * blockDim.x + threadIdx.x;
    if (tid < 256 * 256) {
        g_W0[tid] = __float2bfloat16(fc0w[tid]);
    } else if (tid < 256 * 256 + 128 * 256) {
        int t2 = tid - 256 * 256;
        g_W1[t2] = __float2bfloat16(fc1w[t2]);
    }
}

__global__ void k_embed(const int* __restrict__ x, const float* __restrict__ emb) {
    int tid = blockIdx.x * blockDim.x + threadIdx.x;
    if (tid >= NN * 32) return;
    int n = tid >> 5, j = tid & 31;
    const float4* e4 = (const float4*)emb;
    float4 v = e4[(size_t)x[n] * 32 + j];
    bf162 b0 = __floats2bfloat162_rn(v.x, v.y);
    bf162 b1 = __floats2bfloat162_rn(v.z, v.w);
    uint2 u = make_uint2(*(unsigned*)&b0, *(unsigned*)&b1);
    *(uint2*)(&g_hb[0][(size_t)n * DF + j * 4]) = u;
}

// ---------------- CSR pull: per-dst mean aggregation -> AGG row (bf16) --------
__global__ void k_pull(const bf16* __restrict__ h) {
    int node = (blockIdx.x * blockDim.x + threadIdx.x) >> 5;
    int lane = threadIdx.x & 31;
    if (node >= NN) return;
    int beg = g_rowptr[node];
    int end = g_rowptr[node + 1];
    const uint2* h2 = (const uint2*)h;  // 8B = 4 bf16 per lane

    float4 z = make_float4(0.f, 0.f, 0.f, 0.f);
    float4 a0 = z, a1 = z, a2 = z, a3 = z, a4 = z, a5 = z, a6 = z;

    for (int e = beg; e < end; ++e) {
        int p = g_packed[e];
        int src = p & 0xFFFFF;
        int t = p >> 20;
        uint2 u = h2[(size_t)src * 32 + lane];
        float2 f0 = __bfloat1622float2(*(bf162*)&u.x);
        float2 f1 = __bfloat1622float2(*(bf162*)&u.y);
        switch (t) {
            case 0: a0.x += f0.x; a0.y += f0.y; a0.z += f1.x; a0.w += f1.y; break;
            case 1: a1.x += f0.x; a1.y += f0.y; a1.z += f1.x; a1.w += f1.y; break;
            case 2: a2.x += f0.x; a2.y += f0.y; a2.z += f1.x; a2.w += f1.y; break;
            case 3: a3.x += f0.x; a3.y += f0.y; a3.z += f1.x; a3.w += f1.y; break;
            case 4: a4.x += f0.x; a4.y += f0.y; a4.z += f1.x; a4.w += f1.y; break;
            case 5: a5.x += f0.x; a5.y += f0.y; a5.z += f1.x; a5.w += f1.y; break;
            default: a6.x += f0.x; a6.y += f0.y; a6.z += f1.x; a6.w += f1.y; break;
        }
    }

    uint2* rowq = (uint2*)(g_agg + (size_t)node * KAGG);
    rowq[lane] = h2[(size_t)node * 32 + lane];  // root copy (already bf16)
    const float* icp = g_invc + node * RR;
#define ST_REL(ix, av)                                                     \
    {                                                                      \
        float ic = icp[ix];                                                \
        bf162 p0 = __floats2bfloat162_rn(av.x * ic, av.y * ic);            \
        bf162 p1 = __floats2bfloat162_rn(av.z * ic, av.w * ic);            \
        rowq[32 + (ix)*32 + lane] = make_uint2(*(unsigned*)&p0, *(unsigned*)&p1); \
    }
    ST_REL(0, a0) ST_REL(1, a1) ST_REL(2, a2) ST_REL(3, a3)
    ST_REL(4, a4) ST_REL(5, a5) ST_REL(6, a6)
#undef ST_REL
}

// ---------------- bf16 GEMM: C[M,N] = A[M,K] @ B[N,K]^T, fused epilogue --------
// blockDim 256 (8 warps), CTA tile 128x128, warp tile 32x64, BK=32
// A row-major bf16 (lda=K), B [N][K] row-major bf16 (weights natural layout).
#define SMS 40  // smem row stride in bf16 elems (80B) - conflict-free for ldmatrix
__global__ void k_gemm(const bf16* __restrict__ A, const bf16* __restrict__ B,
                       const float* __restrict__ scale, const float* __restrict__ shift,
                       bf16* __restrict__ C, int M, int K, int Nt, int relu) {
    __shared__ __align__(16) bf16 As[128 * SMS];
    __shared__ __align__(16) bf16 Bs[128 * SMS];

    int tid = threadIdx.x;
    int wid = tid >> 5;
    int lane = tid & 31;
    int wm = wid & 3;        // 0..3 (M)
    int wn = wid >> 2;       // 0..1 (N)
    int g = lane >> 2;
    int tg = lane & 3;

    int bm = blockIdx.x * 128;
    int nb = blockIdx.y * 128;

    uint32_t sAs = (uint32_t)__cvta_generic_to_shared(As);
    uint32_t sBs = (uint32_t)__cvta_generic_to_shared(Bs);

    float acc[2][8][4];
#pragma unroll
    for (int i = 0; i < 2; i++)
#pragma unroll
        for (int j = 0; j < 8; j++)
#pragma unroll
            for (int k = 0; k < 4; k++) acc[i][j][k] = 0.f;

    // ldmatrix source addresses (constant across K-tiles up to kk offset)
    uint32_t aA = sAs + (uint32_t)(((wm * 32 + (lane & 15)) * SMS + ((lane >> 4) << 3)) * 2);
    uint32_t aB = sBs + (uint32_t)(((wn * 64 + (lane & 7) + ((lane >> 4) & 1) * 8) * SMS +
                                    (((lane >> 3) & 1) << 3)) * 2);

    for (int kt = 0; kt < K; kt += 32) {
        // load A tile 128x32 bf16 (64B/row): 512 slots of 16B
#pragma unroll
        for (int i = 0; i < 2; i++) {
            int id = tid + i * 256;
            int row = id >> 2, seg = id & 3;
            int gr = bm + row;
            uint4 v = make_uint4(0, 0, 0, 0);
            if (gr < M) v = *(const uint4*)(A + (size_t)gr * K + kt + seg * 8);
            *(uint4*)(As + row * SMS + seg * 8) = v;
        }
        // load B tile 128(n) x 32(k)
#pragma unroll
        for (int i = 0; i < 2; i++) {
            int id = tid + i * 256;
            int row = id >> 2, seg = id & 3;
            uint4 v = *(const uint4*)(B + (size_t)(nb + row) * K + kt + seg * 8);
            *(uint4*)(Bs + row * SMS + seg * 8) = v;
        }
        __syncthreads();

#pragma unroll
        for (int ks = 0; ks < 2; ks++) {
            int kk = ks * 16;
            unsigned a[2][4], b[4][4];
#pragma unroll
            for (int fm = 0; fm < 2; fm++)
                ldm_x4(a[fm], aA + (uint32_t)((fm * 16 * SMS + kk) * 2));
#pragma unroll
            for (int fn2 = 0; fn2 < 4; fn2++)
                ldm_x4(b[fn2], aB + (uint32_t)((fn2 * 16 * SMS + kk) * 2));
#pragma unroll
            for (int fm = 0; fm < 2; fm++)
#pragma unroll
                for (int fn2 = 0; fn2 < 4; fn2++) {
                    mma_bf16(acc[fm][fn2 * 2], a[fm], &b[fn2][0]);
                    mma_bf16(acc[fm][fn2 * 2 + 1], a[fm], &b[fn2][2]);
                }
        }
        __syncthreads();
    }

    // epilogue: c0,c1 at (row, col..col+1); c2,c3 at (row+8, col..col+1)
#pragma unroll
    for (int fm = 0; fm < 2; fm++) {
#pragma unroll
        for (int fn = 0; fn < 8; fn++) {
            int r = bm + wm * 32 + fm * 16 + g;
            int c = nb + wn * 64 + fn * 8 + tg * 2;
            float s0 = scale ? scale[c] : 1.0f;
            float s1 = scale ? scale[c + 1] : 1.0f;
            float t0 = shift[c], t1 = shift[c + 1];
            float v0 = acc[fm][fn][0] * s0 + t0;
            float v1 = acc[fm][fn][1] * s1 + t1;
            float v2 = acc[fm][fn][2] * s0 + t0;
            float v3 = acc[fm][fn][3] * s1 + t1;
            if (relu) {
                v0 = fmaxf(v0, 0.f); v1 = fmaxf(v1, 0.f);
                v2 = fmaxf(v2, 0.f); v3 = fmaxf(v3, 0.f);
            }
            if (r < M) {
                bf162 p = __floats2bfloat162_rn(v0, v1);
                *(bf162*)(C + (size_t)r * Nt + c) = p;
            }
            if (r + 8 < M) {
                bf162 p = __floats2bfloat162_rn(v2, v3);
                *(bf162*)(C + (size_t)(r + 8) * Nt + c) = p;
            }
        }
    }
}

// ---------------- head --------------------------------------------------------
__global__ void k_gather(const bf16* __restrict__ h, const int* __restrict__ home,
                         const int* __restrict__ away) {
    int b = (blockIdx.x * blockDim.x + threadIdx.x) >> 5;
    int lane = threadIdx.x & 31;
    if (b >= NBATCH) return;
    const uint2* h2 = (const uint2*)h;
    uint2 hv = h2[(size_t)home[b] * 32 + lane];
    uint2 av = h2[(size_t)away[b] * 32 + lane];
    uint2* G2 = (uint2*)g_G;
    G2[(size_t)b * 64 + lane] = hv;
    G2[(size_t)b * 64 + 32 + lane] = av;
}

__global__ void k_head(const float* __restrict__ fc2w, const float* __restrict__ fc2b,
                       float* __restrict__ out) {
    int b = (blockIdx.x * blockDim.x + threadIdx.x) >> 5;
    int lane = threadIdx.x & 31;
    if (b >= NBATCH) return;
    const uint2* g2 = (const uint2*)g_G2;
    uint2 u = g2[(size_t)b * 32 + lane];
    float2 f0 = __bfloat1622float2(*(bf162*)&u.x);
    float2 f1 = __bfloat1622float2(*(bf162*)&u.y);
    const float4* w4 = (const float4*)fc2w;
    float l[3];
#pragma unroll
    for (int c = 0; c < 3; c++) {
        float4 w = w4[c * 32 + lane];
        float d = f0.x * w.x + f0.y * w.y + f1.x * w.z + f1.y * w.w;
#pragma unroll
        for (int off = 16; off; off >>= 1) d += __shfl_xor_sync(0xffffffffu, d, off);
        l[c] = d + fc2b[c];
    }
    float m = fmaxf(l[0], fmaxf(l[1], l[2]));
    float s = expf(l[0] - m) + expf(l[1] - m) + expf(l[2] - m);
    float ls = m + logf(s);
    if (lane < 3) out[b * 3 + lane] = l[lane] - ls;
}

// ---------------- driver --------------------------------------------------------
extern "C" void kernel_launch(void* const* d_in, const int* in_sizes, int n_in,
                              void* d_out, int out_size) {
    const int* x = (const int*)d_in[0];
    const int* ei = (const int*)d_in[1];
    const int* et = (const int*)d_in[2];
    const int* home = (const int*)d_in[3];
    const int* away = (const int*)d_in[4];
    const float* embed = (const float*)d_in[5];
    const float* rel_w = (const float*)d_in[6];
    const float* root_w = (const float*)d_in[7];
    const float* conv_b = (const float*)d_in[8];
    const float* bn_g = (const float*)d_in[9];
    const float* bn_b = (const float*)d_in[10];
    const float* bn_m = (const float*)d_in[11];
    const float* bn_v = (const float*)d_in[12];
    const float* fc0w = (const float*)d_in[13];
    const float* fc0b = (const float*)d_in[14];
    const float* fc1w = (const float*)d_in[15];
    const float* fc1b = (const float*)d_in[16];
    const float* fc2w = (const float*)d_in[17];
    const float* fc2b = (const float*)d_in[18];
    float* out = (float*)d_out;

    bf16 *p_h, *p_agg, *p_W, *p_W0, *p_W1, *p_G, *p_G1, *p_G2;
    float *p_scale, *p_shift;
    cudaGetSymbolAddress((void**)&p_h, g_hb);
    cudaGetSymbolAddress((void**)&p_agg, g_agg);
    cudaGetSymbolAddress((void**)&p_W, g_W);
    cudaGetSymbolAddress((void**)&p_scale, g_scale);
    cudaGetSymbolAddress((void**)&p_shift, g_shift);
    cudaGetSymbolAddress((void**)&p_W0, g_W0);
    cudaGetSymbolAddress((void**)&p_W1, g_W1);
    cudaGetSymbolAddress((void**)&p_G, g_G);
    cudaGetSymbolAddress((void**)&p_G1, g_G1);
    cudaGetSymbolAddress((void**)&p_G2, g_G2);

    // graph build
    k_zero<<<(NN * RR + 255) / 256, 256>>>();
    k_hist<<<(NE + 255) / 256, 256>>>(ei, et);
    k_scanA<<<NBLK, 256>>>();
    k_scanB<<<1, 512>>>();
    k_scanC<<<NBLK, 256>>>();
    k_scatter<<<(NE + 255) / 256, 256>>>(ei, et);

    // parameter prep
    k_prep_w<<<(3 * KAGG * DF + 255) / 256, 256>>>(rel_w, root_w);
    k_prep_bn<<<2, 256>>>(conv_b, bn_g, bn_b, bn_m, bn_v);
    k_prep_fc<<<(256 * 256 + 128 * 256 + 255) / 256, 256>>>(fc0w, fc1w);
    k_embed<<<(NN * 32 + 255) / 256, 256>>>(x, embed);

    // 3 RGCN layers
    bf16* hcur = p_h;
    bf16* hnxt = p_h + (size_t)NN * DF;
    for (int l = 0; l < 3; l++) {
        k_pull<<<(NN + 7) / 8, 256>>>(hcur);
        k_gemm<<<dim3((NN + 127) / 128, 1), 256>>>(
            p_agg, p_W + (size_t)l * KAGG * DF, p_scale + l * DF, p_shift + l * DF,
            hnxt, NN, KAGG, DF, (l < 2) ? 1 : 0);
        bf16* tmp = hcur; hcur = hnxt; hnxt = tmp;
    }

    // head MLP
    k_gather<<<(NBATCH * 32 + 255) / 256, 256>>>(hcur, home, away);
    k_gemm<<<dim3(NBATCH / 128, 2), 256>>>(p_G, p_W0, nullptr, fc0b, p_G1,
                                           NBATCH, 256, 256, 1);
    k_gemm<<<dim3(NBATCH / 128, 1), 256>>>(p_G1, p_W1, nullptr, fc1b, p_G2,
                                           NBATCH, 256, 128, 1);
    k_head<<<(NBATCH * 32 + 255) / 256, 256>>>(fc2w, fc2b, out);
}

// round 14
// speedup vs baseline: 1.2755x; 1.0349x over previous
#include <cuda_runtime.h>
#include <cuda_bf16.h>
#include <stdint.h>
#include <math.h>

#define NN 100000
#define NE 1600000
#define DF 128
#define RR 7
#define NBATCH 4096
#define KAGG ((RR + 1) * DF)          // 1024
#define NB2 ((NN * RR + 255) / 256)   // 2735 blocks over buckets

typedef __nv_bfloat16 bf16;
typedef __nv_bfloat162 bf162;

// ---------------- persistent scratch (device globals; no allocs) -------------
static __device__ __align__(16) bf16 g_hb[2][(size_t)NN * DF]; // ping-pong features
static __device__ int   g_packed[NE];                   // src, bucket-CSR order
static __device__ int   g_rowptr2[NN * RR + 1];
static __device__ int   g_fill2[NN * RR];
static __device__ int   g_cnt[NN * RR];
static __device__ int   g_blocksum2[NB2 + 1];
static __device__ __align__(16) bf16 g_W[3 * KAGG * DF]; // fused weights [l][o][k]
static __device__ float g_scale[3 * DF];
static __device__ float g_shift[3 * DF];
static __device__ __align__(16) bf16 g_W0[256 * 256];   // fc0_w [out][in]
static __device__ __align__(16) bf16 g_W1[128 * 256];   // fc1_w [out][in]
static __device__ __align__(16) bf16 g_G [NBATCH * 256];
static __device__ __align__(16) bf16 g_G1[NBATCH * 256];
static __device__ __align__(16) bf16 g_G2[NBATCH * 128];

// ---------------- helpers ----------------------------------------------------
__device__ __forceinline__ void mma_bf16(float* c, const unsigned* a, const unsigned* b) {
    asm volatile(
        "mma.sync.aligned.m16n8k16.row.col.f32.bf16.bf16.f32 "
        "{%0,%1,%2,%3},{%4,%5,%6,%7},{%8,%9},{%0,%1,%2,%3};"
        : "+f"(c[0]), "+f"(c[1]), "+f"(c[2]), "+f"(c[3])
        : "r"(a[0]), "r"(a[1]), "r"(a[2]), "r"(a[3]), "r"(b[0]), "r"(b[1]));
}
__device__ __forceinline__ void ldm_x4(unsigned* r, uint32_t addr) {
    asm volatile("ldmatrix.sync.aligned.m8n8.x4.shared.b16 {%0,%1,%2,%3},[%4];"
                 : "=r"(r[0]), "=r"(r[1]), "=r"(r[2]), "=r"(r[3]) : "r"(addr));
}

// ---------------- graph build: bucket CSR over (node, relation) ---------------
__global__ void k_zero() {
    int i = blockIdx.x * blockDim.x + threadIdx.x;
    if (i < NN * RR) g_cnt[i] = 0;
}

__global__ void k_hist(const int* __restrict__ ei, const int* __restrict__ et) {
    int e = blockIdx.x * blockDim.x + threadIdx.x;
    if (e >= NE) return;
    atomicAdd(&g_cnt[ei[NE + e] * RR + et[e]], 1);
}

__global__ void k2_scanA() {  // per-block sums of cnt
    int tid = threadIdx.x, lane = tid & 31, w = tid >> 5;
    int i = blockIdx.x * 256 + tid;
    int v = (i < NN * RR) ? g_cnt[i] : 0;
#pragma unroll
    for (int off = 16; off; off >>= 1) v += __shfl_xor_sync(~0u, v, off);
    __shared__ int sw[8];
    if (lane == 0) sw[w] = v;
    __syncthreads();
    if (tid == 0) {
        int s = 0;
#pragma unroll
        for (int k = 0; k < 8; k++) s += sw[k];
        g_blocksum2[blockIdx.x] = s;
    }
}

__global__ void k2_scanB() {  // single-block exclusive scan of NB2 block sums
    __shared__ int sw[32];
    __shared__ int carry;
    int tid = threadIdx.x, lane = tid & 31, w = tid >> 5;
    if (tid == 0) carry = 0;
    __syncthreads();
    for (int base = 0; base < NB2; base += 1024) {
        int i = base + tid;
        int v = (i < NB2) ? g_blocksum2[i] : 0;
        int x = v;
#pragma unroll
        for (int off = 1; off < 32; off <<= 1) {
            int t = __shfl_up_sync(~0u, x, off);
            if (lane >= off) x += t;
        }
        if (lane == 31) sw[w] = x;
        __syncthreads();
        if (w == 0) {
            int y = sw[lane];
#pragma unroll
            for (int off = 1; off < 32; off <<= 1) {
                int t = __shfl_up_sync(~0u, y, off);
                if (lane >= off) y += t;
            }
            sw[lane] = y;
        }
        __syncthreads();
        int woff = (w > 0) ? sw[w - 1] : 0;
        int cur = carry;
        if (i < NB2) g_blocksum2[i] = cur + woff + x - v;
        __syncthreads();
        if (tid == 1023) carry = cur + sw[31];
        __syncthreads();
    }
    if (tid == 0) g_rowptr2[NN * RR] = carry;
}

__global__ void k2_scanC() {  // final bucket rowptr/fill
    int tid = threadIdx.x, lane = tid & 31, w = tid >> 5;
    int i = blockIdx.x * 256 + tid;
    int v = (i < NN * RR) ? g_cnt[i] : 0;
    int x = v;
#pragma unroll
    for (int off = 1; off < 32; off <<= 1) {
        int t = __shfl_up_sync(~0u, x, off);
        if (lane >= off) x += t;
    }
    __shared__ int sw[8];
    if (lane == 31) sw[w] = x;
    __syncthreads();
    int woff = 0;
    for (int k = 0; k < w; k++) woff += sw[k];
    int excl = g_blocksum2[blockIdx.x] + woff + x - v;
    if (i < NN * RR) { g_rowptr2[i] = excl; g_fill2[i] = excl; }
}

__global__ void k_scatter(const int* __restrict__ ei, const int* __restrict__ et) {
    int e = blockIdx.x * blockDim.x + threadIdx.x;
    if (e >= NE) return;
    int src = ei[e];
    int bkt = ei[NE + e] * RR + et[e];
    int pos = atomicAdd(&g_fill2[bkt], 1);
    g_packed[pos] = src;
}

// ---------------- parameter prep ---------------------------------------------
// g_W layout: [l][o(128)][k(1024)], k<128 -> root_w[l][k][o], else rel_w[l][r][i][o]
__global__ void k_prep_w(const float* __restrict__ rel_w, const float* __restrict__ root_w) {
    int tid = blockIdx.x * blockDim.x + threadIdx.x;
    if (tid >= 3 * KAGG * DF) return;
    int l = tid / (KAGG * DF);
    int rem = tid % (KAGG * DF);
    int o = rem / KAGG;
    int k = rem % KAGG;
    float v;
    if (k < DF) {
        v = root_w[((size_t)l * DF + k) * DF + o];
    } else {
        int r = (k - DF) >> 7;
        int i = (k - DF) & 127;
        v = rel_w[(((size_t)l * RR + r) * DF + i) * DF + o];
    }
    g_W[tid] = __float2bfloat16(v);
}

__global__ void k_prep_bn(const float* __restrict__ conv_b, const float* __restrict__ bn_g,
                          const float* __restrict__ bn_b, const float* __restrict__ bn_m,
                          const float* __restrict__ bn_v) {
    int tid = blockIdx.x * blockDim.x + threadIdx.x;
    if (tid >= 3 * DF) return;
    int l = tid / DF, d = tid % DF;
    if (l < 2) {
        float s = bn_g[l * DF + d] * rsqrtf(bn_v[l * DF + d] + 1e-5f);
        g_scale[tid] = s;
        g_shift[tid] = (conv_b[l * DF + d] - bn_m[l * DF + d]) * s + bn_b[l * DF + d];
    } else {
        g_scale[tid] = 1.0f;
        g_shift[tid] = conv_b[2 * DF + d];
    }
}

__global__ void k_prep_fc(const float* __restrict__ fc0w, const float* __restrict__ fc1w) {
    int tid = blockIdx.x * blockDim.x + threadIdx.x;
    if (tid < 256 * 256) {
        g_W0[tid] = __float2bfloat16(fc0w[tid]);
    } else if (tid < 256 * 256 + 128 * 256) {
        int t2 = tid - 256 * 256;
        g_W1[t2] = __float2bfloat16(fc1w[t2]);
    }
}

__global__ void k_embed(const int* __restrict__ x, const float* __restrict__ emb) {
    int tid = blockIdx.x * blockDim.x + threadIdx.x;
    if (tid >= NN * 32) return;
    int n = tid >> 5, j = tid & 31;
    const float4* e4 = (const float4*)emb;
    float4 v = e4[(size_t)x[n] * 32 + j];
    bf162 b0 = __floats2bfloat162_rn(v.x, v.y);
    bf162 b1 = __floats2bfloat162_rn(v.z, v.w);
    uint2 u = make_uint2(*(unsigned*)&b0, *(unsigned*)&b1);
    *(uint2*)(&g_hb[0][(size_t)n * DF + j * 4]) = u;
}

// ---------------- fused RGCN layer ---------------------------------------------
// CTA = 128 nodes x 128 out-dims. Loops 8 buckets (root + 7 relations):
//   gather bucket's mean rows -> As (128x128 bf16), load W slice -> Bs, mma-accumulate.
#define SMS2 136  // smem row stride (bf16 elems); pad 8 keeps ldmatrix conflict-free
#define LAYER_SMEM (2 * 128 * SMS2 * 2)

__global__ void __launch_bounds__(256, 2)
k_layer(const bf16* __restrict__ h, const bf16* __restrict__ W,
        const float* __restrict__ scale, const float* __restrict__ shift,
        bf16* __restrict__ hout, int relu) {
    extern __shared__ __align__(16) bf16 smem[];
    bf16* As = smem;
    bf16* Bs = smem + 128 * SMS2;

    int tid = threadIdx.x;
    int wid = tid >> 5;
    int lane = tid & 31;
    int wm = wid & 3;
    int wn = wid >> 2;
    int g = lane >> 2;
    int tg = lane & 3;
    int bm = blockIdx.x * 128;

    const uint2* h2 = (const uint2*)h;

    uint32_t sAs = (uint32_t)__cvta_generic_to_shared(As);
    uint32_t sBs = (uint32_t)__cvta_generic_to_shared(Bs);
    uint32_t aA = sAs + (uint32_t)(((wm * 32 + (lane & 15)) * SMS2 + ((lane >> 4) << 3)) * 2);
    uint32_t aB = sBs + (uint32_t)(((wn * 64 + (lane & 7) + ((lane >> 4) & 1) * 8) * SMS2 +
                                    (((lane >> 3) & 1) << 3)) * 2);

    float acc[2][8][4];
#pragma unroll
    for (int i = 0; i < 2; i++)
#pragma unroll
        for (int j = 0; j < 8; j++)
#pragma unroll
            for (int k = 0; k < 4; k++) acc[i][j][k] = 0.f;

    for (int b = 0; b < 8; b++) {
        // ---- stage W slice: Bs[o][kk] = W[o*1024 + b*128 + kk], full 128x128 bf16
        // 128 rows x 16 uint4-segments = 2048 writes -> 8 iterations of 256 threads
#pragma unroll
        for (int i = 0; i < 8; i++) {
            int id = tid + i * 256;
            int o = id >> 4, seg = id & 15;
            uint4 v = *(const uint4*)(W + (size_t)o * KAGG + b * 128 + seg * 8);
            *(uint4*)(Bs + o * SMS2 + seg * 8) = v;
        }

        // ---- gather As: 16 nodes per warp, 4 bf16 per lane
        if (b == 0) {
#pragma unroll
            for (int nl = 0; nl < 16; nl++) {
                int row = wid * 16 + nl;
                int node = bm + row;
                uint2 u = make_uint2(0, 0);
                if (node < NN) u = h2[(size_t)node * 32 + lane];
                *(uint2*)(As + row * SMS2 + lane * 4) = u;
            }
        } else {
            for (int nl = 0; nl < 16; nl++) {
                int row = wid * 16 + nl;
                int node = bm + row;
                float4 a = make_float4(0.f, 0.f, 0.f, 0.f);
                float ic = 0.f;
                if (node < NN) {
                    int bkt = node * RR + (b - 1);
                    int beg = g_rowptr2[bkt];
                    int end = g_rowptr2[bkt + 1];
                    int e = beg;
                    for (; e + 1 < end; e += 2) {
                        int s0 = g_packed[e];
                        int s1 = g_packed[e + 1];
                        uint2 u0 = h2[(size_t)s0 * 32 + lane];
                        uint2 u1 = h2[(size_t)s1 * 32 + lane];
                        float2 p0 = __bfloat1622float2(*(bf162*)&u0.x);
                        float2 p1 = __bfloat1622float2(*(bf162*)&u0.y);
                        float2 q0 = __bfloat1622float2(*(bf162*)&u1.x);
                        float2 q1 = __bfloat1622float2(*(bf162*)&u1.y);
                        a.x += p0.x + q0.x; a.y += p0.y + q0.y;
                        a.z += p1.x + q1.x; a.w += p1.y + q1.y;
                    }
                    if (e < end) {
                        uint2 u0 = h2[(size_t)g_packed[e] * 32 + lane];
                        float2 p0 = __bfloat1622float2(*(bf162*)&u0.x);
                        float2 p1 = __bfloat1622float2(*(bf162*)&u0.y);
                        a.x += p0.x; a.y += p0.y; a.z += p1.x; a.w += p1.y;
                    }
                    int d = end - beg;
                    ic = 1.0f / (float)(d > 1 ? d : 1);
                }
                bf162 o0 = __floats2bfloat162_rn(a.x * ic, a.y * ic);
                bf162 o1 = __floats2bfloat162_rn(a.z * ic, a.w * ic);
                *(uint2*)(As + row * SMS2 + lane * 4) =
                    make_uint2(*(unsigned*)&o0, *(unsigned*)&o1);
            }
        }
        __syncthreads();

        // ---- mma over K=128
#pragma unroll
        for (int ks = 0; ks < 8; ks++) {
            int kk = ks * 16;
            unsigned a[2][4], bb[4][4];
#pragma unroll
            for (int fm = 0; fm < 2; fm++)
                ldm_x4(a[fm], aA + (uint32_t)((fm * 16 * SMS2 + kk) * 2));
#pragma unroll
            for (int fn2 = 0; fn2 < 4; fn2++)
                ldm_x4(bb[fn2], aB + (uint32_t)((fn2 * 16 * SMS2 + kk) * 2));
#pragma unroll
            for (int fm = 0; fm < 2; fm++)
#pragma unroll
                for (int fn2 = 0; fn2 < 4; fn2++) {
                    mma_bf16(acc[fm][fn2 * 2], a[fm], &bb[fn2][0]);
                    mma_bf16(acc[fm][fn2 * 2 + 1], a[fm], &bb[fn2][2]);
                }
        }
        __syncthreads();
    }

    // ---- epilogue: BN fold + relu + bf16 store
#pragma unroll
    for (int fm = 0; fm < 2; fm++) {
#pragma unroll
        for (int fn = 0; fn < 8; fn++) {
            int r = bm + wm * 32 + fm * 16 + g;
            int c = wn * 64 + fn * 8 + tg * 2;
            float s0 = scale[c], s1 = scale[c + 1];
            float t0 = shift[c], t1 = shift[c + 1];
            float v0 = acc[fm][fn][0] * s0 + t0;
            float v1 = acc[fm][fn][1] * s1 + t1;
            float v2 = acc[fm][fn][2] * s0 + t0;
            float v3 = acc[fm][fn][3] * s1 + t1;
            if (relu) {
                v0 = fmaxf(v0, 0.f); v1 = fmaxf(v1, 0.f);
                v2 = fmaxf(v2, 0.f); v3 = fmaxf(v3, 0.f);
            }
            if (r < NN) {
                bf162 p = __floats2bfloat162_rn(v0, v1);
                *(bf162*)(hout + (size_t)r * DF + c) = p;
            }
            if (r + 8 < NN) {
                bf162 p = __floats2bfloat162_rn(v2, v3);
                *(bf162*)(hout + (size_t)(r + 8) * DF + c) = p;
            }
        }
    }
}

// ---------------- small bf16 GEMM for head: C[M,N] = A[M,K] @ B[N,K]^T ---------
#define SMS 40
__global__ void k_gemm(const bf16* __restrict__ A, const bf16* __restrict__ B,
                       const float* __restrict__ bias, bf16* __restrict__ C,
                       int M, int K, int Nt, int relu) {
    __shared__ __align__(16) bf16 As[128 * SMS];
    __shared__ __align__(16) bf16 Bs[128 * SMS];

    int tid = threadIdx.x;
    int wid = tid >> 5;
    int lane = tid & 31;
    int wm = wid & 3;
    int wn = wid >> 2;
    int g = lane >> 2;
    int tg = lane & 3;
    int bm = blockIdx.x * 128;
    int nb = blockIdx.y * 128;

    uint32_t sAs = (uint32_t)__cvta_generic_to_shared(As);
    uint32_t sBs = (uint32_t)__cvta_generic_to_shared(Bs);

    float acc[2][8][4];
#pragma unroll
    for (int i = 0; i < 2; i++)
#pragma unroll
        for (int j = 0; j < 8; j++)
#pragma unroll
            for (int k = 0; k < 4; k++) acc[i][j][k] = 0.f;

    uint32_t aA = sAs + (uint32_t)(((wm * 32 + (lane & 15)) * SMS + ((lane >> 4) << 3)) * 2);
    uint32_t aB = sBs + (uint32_t)(((wn * 64 + (lane & 7) + ((lane >> 4) & 1) * 8) * SMS +
                                    (((lane >> 3) & 1) << 3)) * 2);

    for (int kt = 0; kt < K; kt += 32) {
#pragma unroll
        for (int i = 0; i < 2; i++) {
            int id = tid + i * 256;
            int row = id >> 2, seg = id & 3;
            int gr = bm + row;
            uint4 v = make_uint4(0, 0, 0, 0);
            if (gr < M) v = *(const uint4*)(A + (size_t)gr * K + kt + seg * 8);
            *(uint4*)(As + row * SMS + seg * 8) = v;
        }
#pragma unroll
        for (int i = 0; i < 2; i++) {
            int id = tid + i * 256;
            int row = id >> 2, seg = id & 3;
            uint4 v = *(const uint4*)(B + (size_t)(nb + row) * K + kt + seg * 8);
            *(uint4*)(Bs + row * SMS + seg * 8) = v;
        }
        __syncthreads();

#pragma unroll
        for (int ks = 0; ks < 2; ks++) {
            int kk = ks * 16;
            unsigned a[2][4], b[4][4];
#pragma unroll
            for (int fm = 0; fm < 2; fm++)
                ldm_x4(a[fm], aA + (uint32_t)((fm * 16 * SMS + kk) * 2));
#pragma unroll
            for (int fn2 = 0; fn2 < 4; fn2++)
                ldm_x4(b[fn2], aB + (uint32_t)((fn2 * 16 * SMS + kk) * 2));
#pragma unroll
            for (int fm = 0; fm < 2; fm++)
#pragma unroll
                for (int fn2 = 0; fn2 < 4; fn2++) {
                    mma_bf16(acc[fm][fn2 * 2], a[fm], &b[fn2][0]);
                    mma_bf16(acc[fm][fn2 * 2 + 1], a[fm], &b[fn2][2]);
                }
        }
        __syncthreads();
    }

#pragma unroll
    for (int fm = 0; fm < 2; fm++) {
#pragma unroll
        for (int fn = 0; fn < 8; fn++) {
            int r = bm + wm * 32 + fm * 16 + g;
            int c = nb + wn * 64 + fn * 8 + tg * 2;
            float t0 = bias[c], t1 = bias[c + 1];
            float v0 = acc[fm][fn][0] + t0;
            float v1 = acc[fm][fn][1] + t1;
            float v2 = acc[fm][fn][2] + t0;
            float v3 = acc[fm][fn][3] + t1;
            if (relu) {
                v0 = fmaxf(v0, 0.f); v1 = fmaxf(v1, 0.f);
                v2 = fmaxf(v2, 0.f); v3 = fmaxf(v3, 0.f);
            }
            if (r < M) {
                bf162 p = __floats2bfloat162_rn(v0, v1);
                *(bf162*)(C + (size_t)r * Nt + c) = p;
            }
            if (r + 8 < M) {
                bf162 p = __floats2bfloat162_rn(v2, v3);
                *(bf162*)(C + (size_t)(r + 8) * Nt + c) = p;
            }
        }
    }
}

// ---------------- head --------------------------------------------------------
__global__ void k_gather(const bf16* __restrict__ h, const int* __restrict__ home,
                         const int* __restrict__ away) {
    int b = (blockIdx.x * blockDim.x + threadIdx.x) >> 5;
    int lane = threadIdx.x & 31;
    if (b >= NBATCH) return;
    const uint2* h2 = (const uint2*)h;
    uint2 hv = h2[(size_t)home[b] * 32 + lane];
    uint2 av = h2[(size_t)away[b] * 32 + lane];
    uint2* G2 = (uint2*)g_G;
    G2[(size_t)b * 64 + lane] = hv;
    G2[(size_t)b * 64 + 32 + lane] = av;
}

__global__ void k_head(const float* __restrict__ fc2w, const float* __restrict__ fc2b,
                       float* __restrict__ out) {
    int b = (blockIdx.x * blockDim.x + threadIdx.x) >> 5;
    int lane = threadIdx.x & 31;
    if (b >= NBATCH) return;
    const uint2* g2 = (const uint2*)g_G2;
    uint2 u = g2[(size_t)b * 32 + lane];
    float2 f0 = __bfloat1622float2(*(bf162*)&u.x);
    float2 f1 = __bfloat1622float2(*(bf162*)&u.y);
    const float4* w4 = (const float4*)fc2w;
    float l[3];
#pragma unroll
    for (int c = 0; c < 3; c++) {
        float4 w = w4[c * 32 + lane];
        float d = f0.x * w.x + f0.y * w.y + f1.x * w.z + f1.y * w.w;
#pragma unroll
        for (int off = 16; off; off >>= 1) d += __shfl_xor_sync(0xffffffffu, d, off);
        l[c] = d + fc2b[c];
    }
    float m = fmaxf(l[0], fmaxf(l[1], l[2]));
    float s = expf(l[0] - m) + expf(l[1] - m) + expf(l[2] - m);
    float ls = m + logf(s);
    if (lane < 3) out[b * 3 + lane] = l[lane] - ls;
}

// ---------------- driver --------------------------------------------------------
extern "C" void kernel_launch(void* const* d_in, const int* in_sizes, int n_in,
                              void* d_out, int out_size) {
    const int* x = (const int*)d_in[0];
    const int* ei = (const int*)d_in[1];
    const int* et = (const int*)d_in[2];
    const int* home = (const int*)d_in[3];
    const int* away = (const int*)d_in[4];
    const float* embed = (const float*)d_in[5];
    const float* rel_w = (const float*)d_in[6];
    const float* root_w = (const float*)d_in[7];
    const float* conv_b = (const float*)d_in[8];
    const float* bn_g = (const float*)d_in[9];
    const float* bn_b = (const float*)d_in[10];
    const float* bn_m = (const float*)d_in[11];
    const float* bn_v = (const float*)d_in[12];
    const float* fc0w = (const float*)d_in[13];
    const float* fc0b = (const float*)d_in[14];
    const float* fc1w = (const float*)d_in[15];
    const float* fc1b = (const float*)d_in[16];
    const float* fc2w = (const float*)d_in[17];
    const float* fc2b = (const float*)d_in[18];
    float* out = (float*)d_out;

    bf16 *p_h, *p_W, *p_W0, *p_W1, *p_G, *p_G1, *p_G2;
    float *p_scale, *p_shift;
    cudaGetSymbolAddress((void**)&p_h, g_hb);
    cudaGetSymbolAddress((void**)&p_W, g_W);
    cudaGetSymbolAddress((void**)&p_scale, g_scale);
    cudaGetSymbolAddress((void**)&p_shift, g_shift);
    cudaGetSymbolAddress((void**)&p_W0, g_W0);
    cudaGetSymbolAddress((void**)&p_W1, g_W1);
    cudaGetSymbolAddress((void**)&p_G, g_G);
    cudaGetSymbolAddress((void**)&p_G1, g_G1);
    cudaGetSymbolAddress((void**)&p_G2, g_G2);

    cudaFuncSetAttribute(k_layer, cudaFuncAttributeMaxDynamicSharedMemorySize,
                         LAYER_SMEM);

    // graph build: bucket CSR over (node, relation)
    k_zero<<<NB2, 256>>>();
    k_hist<<<(NE + 255) / 256, 256>>>(ei, et);
    k2_scanA<<<NB2, 256>>>();
    k2_scanB<<<1, 1024>>>();
    k2_scanC<<<NB2, 256>>>();
    k_scatter<<<(NE + 255) / 256, 256>>>(ei, et);

    // parameter prep
    k_prep_w<<<(3 * KAGG * DF + 255) / 256, 256>>>(rel_w, root_w);
    k_prep_bn<<<2, 256>>>(conv_b, bn_g, bn_b, bn_m, bn_v);
    k_prep_fc<<<(256 * 256 + 128 * 256 + 255) / 256, 256>>>(fc0w, fc1w);
    k_embed<<<(NN * 32 + 255) / 256, 256>>>(x, embed);

    // 3 fused RGCN layers
    bf16* hcur = p_h;
    bf16* hnxt = p_h + (size_t)NN * DF;
    for (int l = 0; l < 3; l++) {
        k_layer<<<(NN + 127) / 128, 256, LAYER_SMEM>>>(
            hcur, p_W + (size_t)l * KAGG * DF, p_scale + l * DF, p_shift + l * DF,
            hnxt, (l < 2) ? 1 : 0);
        bf16* tmp = hcur; hcur = hnxt; hnxt = tmp;
    }

    // head MLP
    k_gather<<<(NBATCH * 32 + 255) / 256, 256>>>(hcur, home, away);
    k_gemm<<<dim3(NBATCH / 128, 2), 256>>>(p_G, p_W0, fc0b, p_G1, NBATCH, 256, 256, 1);
    k_gemm<<<dim3(NBATCH / 128, 1), 256>>>(p_G1, p_W1, fc1b, p_G2, NBATCH, 256, 128, 1);
    k_head<<<(NBATCH * 32 + 255) / 256, 256>>>(fc2w, fc2b, out);
}

// round 15
// speedup vs baseline: 1.3872x; 1.0876x over previous
#include <cuda_runtime.h>
#include <cuda_bf16.h>
#include <stdint.h>
#include <math.h>

#define NN 100000
#define NE 1600000
#define DF 128
#define RR 7
#define NBATCH 4096
#define KAGG ((RR + 1) * DF)          // 1024
#define NB2 ((NN * RR + 255) / 256)   // 2735 blocks over buckets

typedef __nv_bfloat16 bf16;
typedef __nv_bfloat162 bf162;

// ---------------- persistent scratch (device globals; no allocs) -------------
static __device__ __align__(16) bf16 g_hb[2][(size_t)NN * DF]; // ping-pong features
static __device__ int   g_packed[NE];                   // src, bucket-CSR order
static __device__ int   g_rowptr2[NN * RR + 1];
static __device__ int   g_fill2[NN * RR];
static __device__ int   g_cnt[NN * RR];
static __device__ int   g_blocksum2[NB2 + 1];
static __device__ __align__(16) bf16 g_W[3 * KAGG * DF]; // fused weights [l][o][k]
static __device__ float g_scale[3 * DF];
static __device__ float g_shift[3 * DF];
static __device__ __align__(16) bf16 g_W0[256 * 256];   // fc0_w [out][in]
static __device__ __align__(16) bf16 g_W1[128 * 256];   // fc1_w [out][in]
static __device__ __align__(16) bf16 g_G [NBATCH * 256];
static __device__ __align__(16) bf16 g_G1[NBATCH * 256];
static __device__ __align__(16) bf16 g_G2[NBATCH * 128];

// ---------------- helpers ----------------------------------------------------
__device__ __forceinline__ void mma_bf16(float* c, const unsigned* a, const unsigned* b) {
    asm volatile(
        "mma.sync.aligned.m16n8k16.row.col.f32.bf16.bf16.f32 "
        "{%0,%1,%2,%3},{%4,%5,%6,%7},{%8,%9},{%0,%1,%2,%3};"
        : "+f"(c[0]), "+f"(c[1]), "+f"(c[2]), "+f"(c[3])
        : "r"(a[0]), "r"(a[1]), "r"(a[2]), "r"(a[3]), "r"(b[0]), "r"(b[1]));
}
__device__ __forceinline__ void ldm_x4(unsigned* r, uint32_t addr) {
    asm volatile("ldmatrix.sync.aligned.m8n8.x4.shared.b16 {%0,%1,%2,%3},[%4];"
                 : "=r"(r[0]), "=r"(r[1]), "=r"(r[2]), "=r"(r[3]) : "r"(addr));
}

// ---------------- graph build: bucket CSR over (node, relation) ---------------
__global__ void k_zero() {
    int i = blockIdx.x * blockDim.x + threadIdx.x;
    if (i < NN * RR) g_cnt[i] = 0;
}

__global__ void k_hist(const int* __restrict__ ei, const int* __restrict__ et) {
    int e = blockIdx.x * blockDim.x + threadIdx.x;
    if (e >= NE) return;
    atomicAdd(&g_cnt[ei[NE + e] * RR + et[e]], 1);
}

__global__ void k2_scanA() {  // per-block sums of cnt
    int tid = threadIdx.x, lane = tid & 31, w = tid >> 5;
    int i = blockIdx.x * 256 + tid;
    int v = (i < NN * RR) ? g_cnt[i] : 0;
#pragma unroll
    for (int off = 16; off; off >>= 1) v += __shfl_xor_sync(~0u, v, off);
    __shared__ int sw[8];
    if (lane == 0) sw[w] = v;
    __syncthreads();
    if (tid == 0) {
        int s = 0;
#pragma unroll
        for (int k = 0; k < 8; k++) s += sw[k];
        g_blocksum2[blockIdx.x] = s;
    }
}

__global__ void k2_scanB() {  // single-block exclusive scan of NB2 block sums
    __shared__ int sw[32];
    __shared__ int carry;
    int tid = threadIdx.x, lane = tid & 31, w = tid >> 5;
    if (tid == 0) carry = 0;
    __syncthreads();
    for (int base = 0; base < NB2; base += 1024) {
        int i = base + tid;
        int v = (i < NB2) ? g_blocksum2[i] : 0;
        int x = v;
#pragma unroll
        for (int off = 1; off < 32; off <<= 1) {
            int t = __shfl_up_sync(~0u, x, off);
            if (lane >= off) x += t;
        }
        if (lane == 31) sw[w] = x;
        __syncthreads();
        if (w == 0) {
            int y = sw[lane];
#pragma unroll
            for (int off = 1; off < 32; off <<= 1) {
                int t = __shfl_up_sync(~0u, y, off);
                if (lane >= off) y += t;
            }
            sw[lane] = y;
        }
        __syncthreads();
        int woff = (w > 0) ? sw[w - 1] : 0;
        int cur = carry;
        if (i < NB2) g_blocksum2[i] = cur + woff + x - v;
        __syncthreads();
        if (tid == 1023) carry = cur + sw[31];
        __syncthreads();
    }
    if (tid == 0) g_rowptr2[NN * RR] = carry;
}

__global__ void k2_scanC() {  // final bucket rowptr/fill
    int tid = threadIdx.x, lane = tid & 31, w = tid >> 5;
    int i = blockIdx.x * 256 + tid;
    int v = (i < NN * RR) ? g_cnt[i] : 0;
    int x = v;
#pragma unroll
    for (int off = 1; off < 32; off <<= 1) {
        int t = __shfl_up_sync(~0u, x, off);
        if (lane >= off) x += t;
    }
    __shared__ int sw[8];
    if (lane == 31) sw[w] = x;
    __syncthreads();
    int woff = 0;
    for (int k = 0; k < w; k++) woff += sw[k];
    int excl = g_blocksum2[blockIdx.x] + woff + x - v;
    if (i < NN * RR) { g_rowptr2[i] = excl; g_fill2[i] = excl; }
}

__global__ void k_scatter(const int* __restrict__ ei, const int* __restrict__ et) {
    int e = blockIdx.x * blockDim.x + threadIdx.x;
    if (e >= NE) return;
    int src = ei[e];
    int bkt = ei[NE + e] * RR + et[e];
    int pos = atomicAdd(&g_fill2[bkt], 1);
    g_packed[pos] = src;
}

// ---------------- parameter prep ---------------------------------------------
// g_W layout: [l][o(128)][k(1024)], k<128 -> root_w[l][k][o], else rel_w[l][r][i][o]
__global__ void k_prep_w(const float* __restrict__ rel_w, const float* __restrict__ root_w) {
    int tid = blockIdx.x * blockDim.x + threadIdx.x;
    if (tid >= 3 * KAGG * DF) return;
    int l = tid / (KAGG * DF);
    int rem = tid % (KAGG * DF);
    int o = rem / KAGG;
    int k = rem % KAGG;
    float v;
    if (k < DF) {
        v = root_w[((size_t)l * DF + k) * DF + o];
    } else {
        int r = (k - DF) >> 7;
        int i = (k - DF) & 127;
        v = rel_w[(((size_t)l * RR + r) * DF + i) * DF + o];
    }
    g_W[tid] = __float2bfloat16(v);
}

__global__ void k_prep_bn(const float* __restrict__ conv_b, const float* __restrict__ bn_g,
                          const float* __restrict__ bn_b, const float* __restrict__ bn_m,
                          const float* __restrict__ bn_v) {
    int tid = blockIdx.x * blockDim.x + threadIdx.x;
    if (tid >= 3 * DF) return;
    int l = tid / DF, d = tid % DF;
    if (l < 2) {
        float s = bn_g[l * DF + d] * rsqrtf(bn_v[l * DF + d] + 1e-5f);
        g_scale[tid] = s;
        g_shift[tid] = (conv_b[l * DF + d] - bn_m[l * DF + d]) * s + bn_b[l * DF + d];
    } else {
        g_scale[tid] = 1.0f;
        g_shift[tid] = conv_b[2 * DF + d];
    }
}

__global__ void k_prep_fc(const float* __restrict__ fc0w, const float* __restrict__ fc1w) {
    int tid = blockIdx.x * blockDim.x + threadIdx.x;
    if (tid < 256 * 256) {
        g_W0[tid] = __float2bfloat16(fc0w[tid]);
    } else if (tid < 256 * 256 + 128 * 256) {
        int t2 = tid - 256 * 256;
        g_W1[t2] = __float2bfloat16(fc1w[t2]);
    }
}

__global__ void k_embed(const int* __restrict__ x, const float* __restrict__ emb) {
    int tid = blockIdx.x * blockDim.x + threadIdx.x;
    if (tid >= NN * 32) return;
    int n = tid >> 5, j = tid & 31;
    const float4* e4 = (const float4*)emb;
    float4 v = e4[(size_t)x[n] * 32 + j];
    bf162 b0 = __floats2bfloat162_rn(v.x, v.y);
    bf162 b1 = __floats2bfloat162_rn(v.z, v.w);
    uint2 u = make_uint2(*(unsigned*)&b0, *(unsigned*)&b1);
    *(uint2*)(&g_hb[0][(size_t)n * DF + j * 4]) = u;
}

// ---------------- fused RGCN layer ---------------------------------------------
// CTA = 128 nodes x 128 out-dims. Loops 8 buckets (root + 7 relations):
//   gather bucket's mean rows -> As (128x128 bf16), load W slice -> Bs, mma-accumulate.
// Gather is MLP-optimized: batched rowptr loads, half-warp edge pairing (uint4/lane),
// and packed-index prefetch.
#define SMS2 136  // smem row stride (bf16 elems); pad 8 keeps ldmatrix conflict-free
#define LAYER_SMEM (2 * 128 * SMS2 * 2)

__global__ void __launch_bounds__(256, 2)
k_layer(const bf16* __restrict__ h, const bf16* __restrict__ W,
        const float* __restrict__ scale, const float* __restrict__ shift,
        bf16* __restrict__ hout, int relu) {
    extern __shared__ __align__(16) bf16 smem[];
    bf16* As = smem;
    bf16* Bs = smem + 128 * SMS2;

    int tid = threadIdx.x;
    int wid = tid >> 5;
    int lane = tid & 31;
    int half = lane >> 4;     // 0/1: which half-warp
    int hl = lane & 15;       // position in half (16B chunk index within a row)
    int wm = wid & 3;
    int wn = wid >> 2;
    int g = lane >> 2;
    int tg = lane & 3;
    int bm = blockIdx.x * 128;
    int node0 = bm + wid * 16;

    const uint4* h4 = (const uint4*)h;   // 16 uint4 per 128-dim bf16 row

    uint32_t sAs = (uint32_t)__cvta_generic_to_shared(As);
    uint32_t sBs = (uint32_t)__cvta_generic_to_shared(Bs);
    uint32_t aA = sAs + (uint32_t)(((wm * 32 + (lane & 15)) * SMS2 + ((lane >> 4) << 3)) * 2);
    uint32_t aB = sBs + (uint32_t)(((wn * 64 + (lane & 7) + ((lane >> 4) & 1) * 8) * SMS2 +
                                    (((lane >> 3) & 1) << 3)) * 2);

    float acc[2][8][4];
#pragma unroll
    for (int i = 0; i < 2; i++)
#pragma unroll
        for (int j = 0; j < 8; j++)
#pragma unroll
            for (int k = 0; k < 4; k++) acc[i][j][k] = 0.f;

    for (int b = 0; b < 8; b++) {
        // ---- stage W slice: Bs[o][kk] = W[o*1024 + b*128 + kk], full 128x128 bf16
#pragma unroll
        for (int i = 0; i < 8; i++) {
            int id = tid + i * 256;
            int o = id >> 4, seg = id & 15;
            uint4 v = *(const uint4*)(W + (size_t)o * KAGG + b * 128 + seg * 8);
            *(uint4*)(Bs + o * SMS2 + seg * 8) = v;
        }

        if (b == 0) {
            // root copy: 2 rows per step (one per half-warp), 16B per lane
#pragma unroll
            for (int j = 0; j < 8; j++) {
                int row = wid * 16 + j * 2 + half;
                int node = bm + row;
                uint4 u = make_uint4(0, 0, 0, 0);
                if (node < NN) u = h4[(size_t)node * 16 + hl];
                *(uint4*)(As + row * SMS2 + hl * 8) = u;
            }
        } else {
            // batched rowptr: lane hl loads beg (half 0) / end (half 1) for node0+hl
            int rv = 0;
            {
                int nodeL = node0 + hl;
                if (nodeL < NN) rv = g_rowptr2[nodeL * RR + (b - 1) + half];
            }
            for (int nl = 0; nl < 16; nl++) {
                int row = wid * 16 + nl;
                int beg = __shfl_sync(~0u, rv, nl);
                int end = __shfl_sync(~0u, rv, nl + 16);

                float a0 = 0.f, a1 = 0.f, a2 = 0.f, a3 = 0.f;
                float a4 = 0.f, a5 = 0.f, a6 = 0.f, a7 = 0.f;

                // half-warp pairing: half 0 takes edges beg, beg+2, ...; half 1 beg+1, ...
                int e = beg + half;
                int s = (e < end) ? g_packed[e] : 0;
                while (e < end) {
                    int sc = s;
                    int en = e + 2;
                    if (en < end) s = g_packed[en];   // prefetch next index
                    uint4 u = h4[(size_t)sc * 16 + hl];
                    float2 f0 = __bfloat1622float2(*(bf162*)&u.x);
                    float2 f1 = __bfloat1622float2(*(bf162*)&u.y);
                    float2 f2 = __bfloat1622float2(*(bf162*)&u.z);
                    float2 f3 = __bfloat1622float2(*(bf162*)&u.w);
                    a0 += f0.x; a1 += f0.y; a2 += f1.x; a3 += f1.y;
                    a4 += f2.x; a5 += f2.y; a6 += f3.x; a7 += f3.y;
                    e = en;
                }
                // combine the two halves (same dims, disjoint edge subsets)
                a0 += __shfl_xor_sync(~0u, a0, 16);
                a1 += __shfl_xor_sync(~0u, a1, 16);
                a2 += __shfl_xor_sync(~0u, a2, 16);
                a3 += __shfl_xor_sync(~0u, a3, 16);
                a4 += __shfl_xor_sync(~0u, a4, 16);
                a5 += __shfl_xor_sync(~0u, a5, 16);
                a6 += __shfl_xor_sync(~0u, a6, 16);
                a7 += __shfl_xor_sync(~0u, a7, 16);

                if (half == 0) {
                    int d = end - beg;
                    float ic = 1.0f / (float)(d > 1 ? d : 1);
                    bf162 p0 = __floats2bfloat162_rn(a0 * ic, a1 * ic);
                    bf162 p1 = __floats2bfloat162_rn(a2 * ic, a3 * ic);
                    bf162 p2 = __floats2bfloat162_rn(a4 * ic, a5 * ic);
                    bf162 p3 = __floats2bfloat162_rn(a6 * ic, a7 * ic);
                    uint4 o;
                    o.x = *(unsigned*)&p0; o.y = *(unsigned*)&p1;
                    o.z = *(unsigned*)&p2; o.w = *(unsigned*)&p3;
                    *(uint4*)(As + row * SMS2 + hl * 8) = o;
                }
            }
        }
        __syncthreads();

        // ---- mma over K=128
#pragma unroll
        for (int ks = 0; ks < 8; ks++) {
            int kk = ks * 16;
            unsigned a[2][4], bb[4][4];
#pragma unroll
            for (int fm = 0; fm < 2; fm++)
                ldm_x4(a[fm], aA + (uint32_t)((fm * 16 * SMS2 + kk) * 2));
#pragma unroll
            for (int fn2 = 0; fn2 < 4; fn2++)
                ldm_x4(bb[fn2], aB + (uint32_t)((fn2 * 16 * SMS2 + kk) * 2));
#pragma unroll
            for (int fm = 0; fm < 2; fm++)
#pragma unroll
                for (int fn2 = 0; fn2 < 4; fn2++) {
                    mma_bf16(acc[fm][fn2 * 2], a[fm], &bb[fn2][0]);
                    mma_bf16(acc[fm][fn2 * 2 + 1], a[fm], &bb[fn2][2]);
                }
        }
        __syncthreads();
    }

    // ---- epilogue: BN fold + relu + bf16 store
#pragma unroll
    for (int fm = 0; fm < 2; fm++) {
#pragma unroll
        for (int fn = 0; fn < 8; fn++) {
            int r = bm + wm * 32 + fm * 16 + g;
            int c = wn * 64 + fn * 8 + tg * 2;
            float s0 = scale[c], s1 = scale[c + 1];
            float t0 = shift[c], t1 = shift[c + 1];
            float v0 = acc[fm][fn][0] * s0 + t0;
            float v1 = acc[fm][fn][1] * s1 + t1;
            float v2 = acc[fm][fn][2] * s0 + t0;
            float v3 = acc[fm][fn][3] * s1 + t1;
            if (relu) {
                v0 = fmaxf(v0, 0.f); v1 = fmaxf(v1, 0.f);
                v2 = fmaxf(v2, 0.f); v3 = fmaxf(v3, 0.f);
            }
            if (r < NN) {
                bf162 p = __floats2bfloat162_rn(v0, v1);
                *(bf162*)(hout + (size_t)r * DF + c) = p;
            }
            if (r + 8 < NN) {
                bf162 p = __floats2bfloat162_rn(v2, v3);
                *(bf162*)(hout + (size_t)(r + 8) * DF + c) = p;
            }
        }
    }
}

// ---------------- small bf16 GEMM for head: C[M,N] = A[M,K] @ B[N,K]^T ---------
#define SMS 40
__global__ void k_gemm(const bf16* __restrict__ A, const bf16* __restrict__ B,
                       const float* __restrict__ bias, bf16* __restrict__ C,
                       int M, int K, int Nt, int relu) {
    __shared__ __align__(16) bf16 As[128 * SMS];
    __shared__ __align__(16) bf16 Bs[128 * SMS];

    int tid = threadIdx.x;
    int wid = tid >> 5;
    int lane = tid & 31;
    int wm = wid & 3;
    int wn = wid >> 2;
    int g = lane >> 2;
    int tg = lane & 3;
    int bm = blockIdx.x * 128;
    int nb = blockIdx.y * 128;

    uint32_t sAs = (uint32_t)__cvta_generic_to_shared(As);
    uint32_t sBs = (uint32_t)__cvta_generic_to_shared(Bs);

    float acc[2][8][4];
#pragma unroll
    for (int i = 0; i < 2; i++)
#pragma unroll
        for (int j = 0; j < 8; j++)
#pragma unroll
            for (int k = 0; k < 4; k++) acc[i][j][k] = 0.f;

    uint32_t aA = sAs + (uint32_t)(((wm * 32 + (lane & 15)) * SMS + ((lane >> 4) << 3)) * 2);
    uint32_t aB = sBs + (uint32_t)(((wn * 64 + (lane & 7) + ((lane >> 4) & 1) * 8) * SMS +
                                    (((lane >> 3) & 1) << 3)) * 2);

    for (int kt = 0; kt < K; kt += 32) {
#pragma unroll
        for (int i = 0; i < 2; i++) {
            int id = tid + i * 256;
            int row = id >> 2, seg = id & 3;
            int gr = bm + row;
            uint4 v = make_uint4(0, 0, 0, 0);
            if (gr < M) v = *(const uint4*)(A + (size_t)gr * K + kt + seg * 8);
            *(uint4*)(As + row * SMS + seg * 8) = v;
        }
#pragma unroll
        for (int i = 0; i < 2; i++) {
            int id = tid + i * 256;
            int row = id >> 2, seg = id & 3;
            uint4 v = *(const uint4*)(B + (size_t)(nb + row) * K + kt + seg * 8);
            *(uint4*)(Bs + row * SMS + seg * 8) = v;
        }
        __syncthreads();

#pragma unroll
        for (int ks = 0; ks < 2; ks++) {
            int kk = ks * 16;
            unsigned a[2][4], b[4][4];
#pragma unroll
            for (int fm = 0; fm < 2; fm++)
                ldm_x4(a[fm], aA + (uint32_t)((fm * 16 * SMS + kk) * 2));
#pragma unroll
            for (int fn2 = 0; fn2 < 4; fn2++)
                ldm_x4(b[fn2], aB + (uint32_t)((fn2 * 16 * SMS + kk) * 2));
#pragma unroll
            for (int fm = 0; fm < 2; fm++)
#pragma unroll
                for (int fn2 = 0; fn2 < 4; fn2++) {
                    mma_bf16(acc[fm][fn2 * 2], a[fm], &b[fn2][0]);
                    mma_bf16(acc[fm][fn2 * 2 + 1], a[fm], &b[fn2][2]);
                }
        }
        __syncthreads();
    }

#pragma unroll
    for (int fm = 0; fm < 2; fm++) {
#pragma unroll
        for (int fn = 0; fn < 8; fn++) {
            int r = bm + wm * 32 + fm * 16 + g;
            int c = nb + wn * 64 + fn * 8 + tg * 2;
            float t0 = bias[c], t1 = bias[c + 1];
            float v0 = acc[fm][fn][0] + t0;
            float v1 = acc[fm][fn][1] + t1;
            float v2 = acc[fm][fn][2] + t0;
            float v3 = acc[fm][fn][3] + t1;
            if (relu) {
                v0 = fmaxf(v0, 0.f); v1 = fmaxf(v1, 0.f);
                v2 = fmaxf(v2, 0.f); v3 = fmaxf(v3, 0.f);
            }
            if (r < M) {
                bf162 p = __floats2bfloat162_rn(v0, v1);
                *(bf162*)(C + (size_t)r * Nt + c) = p;
            }
            if (r + 8 < M) {
                bf162 p = __floats2bfloat162_rn(v2, v3);
                *(bf162*)(C + (size_t)(r + 8) * Nt + c) = p;
            }
        }
    }
}

// ---------------- head --------------------------------------------------------
__global__ void k_gather(const bf16* __restrict__ h, const int* __restrict__ home,
                         const int* __restrict__ away) {
    int b = (blockIdx.x * blockDim.x + threadIdx.x) >> 5;
    int lane = threadIdx.x & 31;
    if (b >= NBATCH) return;
    const uint2* h2 = (const uint2*)h;
    uint2 hv = h2[(size_t)home[b] * 32 + lane];
    uint2 av = h2[(size_t)away[b] * 32 + lane];
    uint2* G2 = (uint2*)g_G;
    G2[(size_t)b * 64 + lane] = hv;
    G2[(size_t)b * 64 + 32 + lane] = av;
}

__global__ void k_head(const float* __restrict__ fc2w, const float* __restrict__ fc2b,
                       float* __restrict__ out) {
    int b = (blockIdx.x * blockDim.x + threadIdx.x) >> 5;
    int lane = threadIdx.x & 31;
    if (b >= NBATCH) return;
    const uint2* g2 = (const uint2*)g_G2;
    uint2 u = g2[(size_t)b * 32 + lane];
    float2 f0 = __bfloat1622float2(*(bf162*)&u.x);
    float2 f1 = __bfloat1622float2(*(bf162*)&u.y);
    const float4* w4 = (const float4*)fc2w;
    float l[3];
#pragma unroll
    for (int c = 0; c < 3; c++) {
        float4 w = w4[c * 32 + lane];
        float d = f0.x * w.x + f0.y * w.y + f1.x * w.z + f1.y * w.w;
#pragma unroll
        for (int off = 16; off; off >>= 1) d += __shfl_xor_sync(0xffffffffu, d, off);
        l[c] = d + fc2b[c];
    }
    float m = fmaxf(l[0], fmaxf(l[1], l[2]));
    float s = expf(l[0] - m) + expf(l[1] - m) + expf(l[2] - m);
    float ls = m + logf(s);
    if (lane < 3) out[b * 3 + lane] = l[lane] - ls;
}

// ---------------- driver --------------------------------------------------------
extern "C" void kernel_launch(void* const* d_in, const int* in_sizes, int n_in,
                              void* d_out, int out_size) {
    const int* x = (const int*)d_in[0];
    const int* ei = (const int*)d_in[1];
    const int* et = (const int*)d_in[2];
    const int* home = (const int*)d_in[3];
    const int* away = (const int*)d_in[4];
    const float* embed = (const float*)d_in[5];
    const float* rel_w = (const float*)d_in[6];
    const float* root_w = (const float*)d_in[7];
    const float* conv_b = (const float*)d_in[8];
    const float* bn_g = (const float*)d_in[9];
    const float* bn_b = (const float*)d_in[10];
    const float* bn_m = (const float*)d_in[11];
    const float* bn_v = (const float*)d_in[12];
    const float* fc0w = (const float*)d_in[13];
    const float* fc0b = (const float*)d_in[14];
    const float* fc1w = (const float*)d_in[15];
    const float* fc1b = (const float*)d_in[16];
    const float* fc2w = (const float*)d_in[17];
    const float* fc2b = (const float*)d_in[18];
    float* out = (float*)d_out;

    bf16 *p_h, *p_W, *p_W0, *p_W1, *p_G, *p_G1, *p_G2;
    float *p_scale, *p_shift;
    cudaGetSymbolAddress((void**)&p_h, g_hb);
    cudaGetSymbolAddress((void**)&p_W, g_W);
    cudaGetSymbolAddress((void**)&p_scale, g_scale);
    cudaGetSymbolAddress((void**)&p_shift, g_shift);
    cudaGetSymbolAddress((void**)&p_W0, g_W0);
    cudaGetSymbolAddress((void**)&p_W1, g_W1);
    cudaGetSymbolAddress((void**)&p_G, g_G);
    cudaGetSymbolAddress((void**)&p_G1, g_G1);
    cudaGetSymbolAddress((void**)&p_G2, g_G2);

    cudaFuncSetAttribute(k_layer, cudaFuncAttributeMaxDynamicSharedMemorySize,
                         LAYER_SMEM);

    // graph build: bucket CSR over (node, relation)
    k_zero<<<NB2, 256>>>();
    k_hist<<<(NE + 255) / 256, 256>>>(ei, et);
    k2_scanA<<<NB2, 256>>>();
    k2_scanB<<<1, 1024>>>();
    k2_scanC<<<NB2, 256>>>();
    k_scatter<<<(NE + 255) / 256, 256>>>(ei, et);

    // parameter prep
    k_prep_w<<<(3 * KAGG * DF + 255) / 256, 256>>>(rel_w, root_w);
    k_prep_bn<<<2, 256>>>(conv_b, bn_g, bn_b, bn_m, bn_v);
    k_prep_fc<<<(256 * 256 + 128 * 256 + 255) / 256, 256>>>(fc0w, fc1w);
    k_embed<<<(NN * 32 + 255) / 256, 256>>>(x, embed);

    // 3 fused RGCN layers
    bf16* hcur = p_h;
    bf16* hnxt = p_h + (size_t)NN * DF;
    for (int l = 0; l < 3; l++) {
        k_layer<<<(NN + 127) / 128, 256, LAYER_SMEM>>>(
            hcur, p_W + (size_t)l * KAGG * DF, p_scale + l * DF, p_shift + l * DF,
            hnxt, (l < 2) ? 1 : 0);
        bf16* tmp = hcur; hcur = hnxt; hnxt = tmp;
    }

    // head MLP
    k_gather<<<(NBATCH * 32 + 255) / 256, 256>>>(hcur, home, away);
    k_gemm<<<dim3(NBATCH / 128, 2), 256>>>(p_G, p_W0, fc0b, p_G1, NBATCH, 256, 256, 1);
    k_gemm<<<dim3(NBATCH / 128, 1), 256>>>(p_G1, p_W1, fc1b, p_G2, NBATCH, 256, 128, 1);
    k_head<<<(NBATCH * 32 + 255) / 256, 256>>>(fc2w, fc2b, out);
}

// round 16
// speedup vs baseline: 1.7666x; 1.2735x over previous
#include <cuda_runtime.h>
#include <cuda_bf16.h>
#include <stdint.h>
#include <math.h>

#define NN 100000
#define NE 1600000
#define DF 128
#define RR 7
#define NBATCH 4096
#define KAGG ((RR + 1) * DF)          // 1024
#define NB2 ((NN * RR + 255) / 256)   // 2735 blocks over buckets

typedef __nv_bfloat16 bf16;
typedef __nv_bfloat162 bf162;

// ---------------- persistent scratch (device globals; no allocs) -------------
static __device__ __align__(16) bf16 g_hb[2][(size_t)NN * DF]; // ping-pong features
static __device__ int   g_packed[NE];                   // src, bucket-CSR order
static __device__ int   g_rowptr2[NN * RR + 1];
static __device__ int   g_fill2[NN * RR];
static __device__ int   g_cnt[NN * RR];
static __device__ int   g_blocksum2[NB2 + 1];
static __device__ __align__(16) bf16 g_W[3 * KAGG * DF]; // fused weights [l][o][k]
static __device__ float g_scale[3 * DF];
static __device__ float g_shift[3 * DF];
static __device__ __align__(16) bf16 g_W0[256 * 256];   // fc0_w [out][in]
static __device__ __align__(16) bf16 g_W1[128 * 256];   // fc1_w [out][in]
static __device__ __align__(16) bf16 g_G [NBATCH * 256];
static __device__ __align__(16) bf16 g_G1[NBATCH * 256];
static __device__ __align__(16) bf16 g_G2[NBATCH * 128];

// ---------------- helpers ----------------------------------------------------
__device__ __forceinline__ void mma_bf16(float* c, const unsigned* a, const unsigned* b) {
    asm volatile(
        "mma.sync.aligned.m16n8k16.row.col.f32.bf16.bf16.f32 "
        "{%0,%1,%2,%3},{%4,%5,%6,%7},{%8,%9},{%0,%1,%2,%3};"
        : "+f"(c[0]), "+f"(c[1]), "+f"(c[2]), "+f"(c[3])
        : "r"(a[0]), "r"(a[1]), "r"(a[2]), "r"(a[3]), "r"(b[0]), "r"(b[1]));
}
__device__ __forceinline__ void ldm_x4(unsigned* r, uint32_t addr) {
    asm volatile("ldmatrix.sync.aligned.m8n8.x4.shared.b16 {%0,%1,%2,%3},[%4];"
                 : "=r"(r[0]), "=r"(r[1]), "=r"(r[2]), "=r"(r[3]) : "r"(addr));
}

// ---------------- graph build: bucket CSR over (node, relation) ---------------
__global__ void k_zero() {
    int i = blockIdx.x * blockDim.x + threadIdx.x;
    if (i < NN * RR) g_cnt[i] = 0;
}

__global__ void k_hist(const int* __restrict__ ei, const int* __restrict__ et) {
    int e = blockIdx.x * blockDim.x + threadIdx.x;
    if (e >= NE) return;
    atomicAdd(&g_cnt[ei[NE + e] * RR + et[e]], 1);
}

__global__ void k2_scanA() {  // per-block sums of cnt
    int tid = threadIdx.x, lane = tid & 31, w = tid >> 5;
    int i = blockIdx.x * 256 + tid;
    int v = (i < NN * RR) ? g_cnt[i] : 0;
#pragma unroll
    for (int off = 16; off; off >>= 1) v += __shfl_xor_sync(~0u, v, off);
    __shared__ int sw[8];
    if (lane == 0) sw[w] = v;
    __syncthreads();
    if (tid == 0) {
        int s = 0;
#pragma unroll
        for (int k = 0; k < 8; k++) s += sw[k];
        g_blocksum2[blockIdx.x] = s;
    }
}

__global__ void k2_scanB() {  // single-block exclusive scan of NB2 block sums
    __shared__ int sw[32];
    __shared__ int carry;
    int tid = threadIdx.x, lane = tid & 31, w = tid >> 5;
    if (tid == 0) carry = 0;
    __syncthreads();
    for (int base = 0; base < NB2; base += 1024) {
        int i = base + tid;
        int v = (i < NB2) ? g_blocksum2[i] : 0;
        int x = v;
#pragma unroll
        for (int off = 1; off < 32; off <<= 1) {
            int t = __shfl_up_sync(~0u, x, off);
            if (lane >= off) x += t;
        }
        if (lane == 31) sw[w] = x;
        __syncthreads();
        if (w == 0) {
            int y = sw[lane];
#pragma unroll
            for (int off = 1; off < 32; off <<= 1) {
                int t = __shfl_up_sync(~0u, y, off);
                if (lane >= off) y += t;
            }
            sw[lane] = y;
        }
        __syncthreads();
        int woff = (w > 0) ? sw[w - 1] : 0;
        int cur = carry;
        if (i < NB2) g_blocksum2[i] = cur + woff + x - v;
        __syncthreads();
        if (tid == 1023) carry = cur + sw[31];
        __syncthreads();
    }
    if (tid == 0) g_rowptr2[NN * RR] = carry;
}

__global__ void k2_scanC() {  // final bucket rowptr/fill
    int tid = threadIdx.x, lane = tid & 31, w = tid >> 5;
    int i = blockIdx.x * 256 + tid;
    int v = (i < NN * RR) ? g_cnt[i] : 0;
    int x = v;
#pragma unroll
    for (int off = 1; off < 32; off <<= 1) {
        int t = __shfl_up_sync(~0u, x, off);
        if (lane >= off) x += t;
    }
    __shared__ int sw[8];
    if (lane == 31) sw[w] = x;
    __syncthreads();
    int woff = 0;
    for (int k = 0; k < w; k++) woff += sw[k];
    int excl = g_blocksum2[blockIdx.x] + woff + x - v;
    if (i < NN * RR) { g_rowptr2[i] = excl; g_fill2[i] = excl; }
}

__global__ void k_scatter(const int* __restrict__ ei, const int* __restrict__ et) {
    int e = blockIdx.x * blockDim.x + threadIdx.x;
    if (e >= NE) return;
    int src = ei[e];
    int bkt = ei[NE + e] * RR + et[e];
    int pos = atomicAdd(&g_fill2[bkt], 1);
    g_packed[pos] = src;
}

// ---------------- parameter prep ---------------------------------------------
// g_W layout: [l][o(128)][k(1024)], k<128 -> root_w[l][k][o], else rel_w[l][r][i][o]
__global__ void k_prep_w(const float* __restrict__ rel_w, const float* __restrict__ root_w) {
    int tid = blockIdx.x * blockDim.x + threadIdx.x;
    if (tid >= 3 * KAGG * DF) return;
    int l = tid / (KAGG * DF);
    int rem = tid % (KAGG * DF);
    int o = rem / KAGG;
    int k = rem % KAGG;
    float v;
    if (k < DF) {
        v = root_w[((size_t)l * DF + k) * DF + o];
    } else {
        int r = (k - DF) >> 7;
        int i = (k - DF) & 127;
        v = rel_w[(((size_t)l * RR + r) * DF + i) * DF + o];
    }
    g_W[tid] = __float2bfloat16(v);
}

__global__ void k_prep_bn(const float* __restrict__ conv_b, const float* __restrict__ bn_g,
                          const float* __restrict__ bn_b, const float* __restrict__ bn_m,
                          const float* __restrict__ bn_v) {
    int tid = blockIdx.x * blockDim.x + threadIdx.x;
    if (tid >= 3 * DF) return;
    int l = tid / DF, d = tid % DF;
    if (l < 2) {
        float s = bn_g[l * DF + d] * rsqrtf(bn_v[l * DF + d] + 1e-5f);
        g_scale[tid] = s;
        g_shift[tid] = (conv_b[l * DF + d] - bn_m[l * DF + d]) * s + bn_b[l * DF + d];
    } else {
        g_scale[tid] = 1.0f;
        g_shift[tid] = conv_b[2 * DF + d];
    }
}

__global__ void k_prep_fc(const float* __restrict__ fc0w, const float* __restrict__ fc1w) {
    int tid = blockIdx.x * blockDim.x + threadIdx.x;
    if (tid < 256 * 256) {
        g_W0[tid] = __float2bfloat16(fc0w[tid]);
    } else if (tid < 256 * 256 + 128 * 256) {
        int t2 = tid - 256 * 256;
        g_W1[t2] = __float2bfloat16(fc1w[t2]);
    }
}

__global__ void k_embed(const int* __restrict__ x, const float* __restrict__ emb) {
    int tid = blockIdx.x * blockDim.x + threadIdx.x;
    if (tid >= NN * 32) return;
    int n = tid >> 5, j = tid & 31;
    const float4* e4 = (const float4*)emb;
    float4 v = e4[(size_t)x[n] * 32 + j];
    bf162 b0 = __floats2bfloat162_rn(v.x, v.y);
    bf162 b1 = __floats2bfloat162_rn(v.z, v.w);
    uint2 u = make_uint2(*(unsigned*)&b0, *(unsigned*)&b1);
    *(uint2*)(&g_hb[0][(size_t)n * DF + j * 4]) = u;
}

// ---------------- fused RGCN layer ---------------------------------------------
// 512 threads (16 warps), CTA tile 128x128, warp mma tile 32x32.
// Each warp gathers 8 nodes per bucket (half-warp edge-parity, uint4/lane rows).
#define SMS2 136  // smem row stride (bf16 elems); pad 8 keeps ldmatrix conflict-free
#define LAYER_SMEM (2 * 128 * SMS2 * 2)

__global__ void __launch_bounds__(512, 2)
k_layer(const bf16* __restrict__ h, const bf16* __restrict__ W,
        const float* __restrict__ scale, const float* __restrict__ shift,
        bf16* __restrict__ hout, int relu) {
    extern __shared__ __align__(16) bf16 smem[];
    bf16* As = smem;
    bf16* Bs = smem + 128 * SMS2;

    int tid = threadIdx.x;
    int wid = tid >> 5;      // 0..15
    int lane = tid & 31;
    int half = lane >> 4;    // 0/1
    int hl = lane & 15;      // 16B chunk index within a row
    int wm = wid & 3;        // M group (32 rows)
    int wn = wid >> 2;       // N group (32 cols), 0..3
    int g = lane >> 2;
    int tg = lane & 3;
    int bm = blockIdx.x * 128;
    int node0 = bm + wid * 8;

    const uint4* h4 = (const uint4*)h;   // 16 uint4 per 128-dim bf16 row

    uint32_t sAs = (uint32_t)__cvta_generic_to_shared(As);
    uint32_t sBs = (uint32_t)__cvta_generic_to_shared(Bs);
    uint32_t aA = sAs + (uint32_t)(((wm * 32 + (lane & 15)) * SMS2 + ((lane >> 4) << 3)) * 2);
    uint32_t aB = sBs + (uint32_t)(((wn * 32 + (lane & 7) + ((lane >> 4) & 1) * 8) * SMS2 +
                                    (((lane >> 3) & 1) << 3)) * 2);

    float acc[2][4][4];
#pragma unroll
    for (int i = 0; i < 2; i++)
#pragma unroll
        for (int j = 0; j < 4; j++)
#pragma unroll
            for (int k = 0; k < 4; k++) acc[i][j][k] = 0.f;

    for (int b = 0; b < 8; b++) {
        // ---- stage W slice: full 128x128 bf16 = 2048 uint4 -> 4 iters of 512
#pragma unroll
        for (int i = 0; i < 4; i++) {
            int id = tid + i * 512;
            int o = id >> 4, seg = id & 15;
            uint4 v = *(const uint4*)(W + (size_t)o * KAGG + b * 128 + seg * 8);
            *(uint4*)(Bs + o * SMS2 + seg * 8) = v;
        }

        if (b == 0) {
            // root copy: 8 rows per warp, 2 per step (one per half), 16B/lane
#pragma unroll
            for (int j = 0; j < 4; j++) {
                int row = wid * 8 + j * 2 + half;
                int node = bm + row;
                uint4 u = make_uint4(0, 0, 0, 0);
                if (node < NN) u = h4[(size_t)node * 16 + hl];
                *(uint4*)(As + row * SMS2 + hl * 8) = u;
            }
        } else {
            // batched rowptr: lanes 0..15 load beg/end for the warp's 8 nodes
            int rv = 0;
            if (lane < 16) {
                int nodeL = node0 + (lane & 7);
                if (nodeL < NN)
                    rv = g_rowptr2[nodeL * RR + (b - 1) + (lane >> 3)];
            }
            for (int nl = 0; nl < 8; nl++) {
                int row = wid * 8 + nl;
                int beg = __shfl_sync(~0u, rv, nl);
                int end = __shfl_sync(~0u, rv, nl + 8);

                float a0 = 0.f, a1 = 0.f, a2 = 0.f, a3 = 0.f;
                float a4 = 0.f, a5 = 0.f, a6 = 0.f, a7 = 0.f;

                // half-warp pairing: half 0 takes edges beg, beg+2, ...; half 1 beg+1, ...
                int e = beg + half;
                int s = (e < end) ? g_packed[e] : 0;
                while (e < end) {
                    int sc = s;
                    int en = e + 2;
                    if (en < end) s = g_packed[en];   // prefetch next index
                    uint4 u = h4[(size_t)sc * 16 + hl];
                    float2 f0 = __bfloat1622float2(*(bf162*)&u.x);
                    float2 f1 = __bfloat1622float2(*(bf162*)&u.y);
                    float2 f2 = __bfloat1622float2(*(bf162*)&u.z);
                    float2 f3 = __bfloat1622float2(*(bf162*)&u.w);
                    a0 += f0.x; a1 += f0.y; a2 += f1.x; a3 += f1.y;
                    a4 += f2.x; a5 += f2.y; a6 += f3.x; a7 += f3.y;
                    e = en;
                }
                // combine halves (disjoint edge subsets, same dims)
                a0 += __shfl_xor_sync(~0u, a0, 16);
                a1 += __shfl_xor_sync(~0u, a1, 16);
                a2 += __shfl_xor_sync(~0u, a2, 16);
                a3 += __shfl_xor_sync(~0u, a3, 16);
                a4 += __shfl_xor_sync(~0u, a4, 16);
                a5 += __shfl_xor_sync(~0u, a5, 16);
                a6 += __shfl_xor_sync(~0u, a6, 16);
                a7 += __shfl_xor_sync(~0u, a7, 16);

                if (half == 0) {
                    int d = end - beg;
                    float ic = 1.0f / (float)(d > 1 ? d : 1);
                    bf162 p0 = __floats2bfloat162_rn(a0 * ic, a1 * ic);
                    bf162 p1 = __floats2bfloat162_rn(a2 * ic, a3 * ic);
                    bf162 p2 = __floats2bfloat162_rn(a4 * ic, a5 * ic);
                    bf162 p3 = __floats2bfloat162_rn(a6 * ic, a7 * ic);
                    uint4 o;
                    o.x = *(unsigned*)&p0; o.y = *(unsigned*)&p1;
                    o.z = *(unsigned*)&p2; o.w = *(unsigned*)&p3;
                    *(uint4*)(As + row * SMS2 + hl * 8) = o;
                }
            }
        }
        __syncthreads();

        // ---- mma over K=128 (warp tile 32x32)
#pragma unroll
        for (int ks = 0; ks < 8; ks++) {
            int kk = ks * 16;
            unsigned a[2][4], bb[2][4];
#pragma unroll
            for (int fm = 0; fm < 2; fm++)
                ldm_x4(a[fm], aA + (uint32_t)((fm * 16 * SMS2 + kk) * 2));
#pragma unroll
            for (int fn2 = 0; fn2 < 2; fn2++)
                ldm_x4(bb[fn2], aB + (uint32_t)((fn2 * 16 * SMS2 + kk) * 2));
#pragma unroll
            for (int fm = 0; fm < 2; fm++)
#pragma unroll
                for (int fn2 = 0; fn2 < 2; fn2++) {
                    mma_bf16(acc[fm][fn2 * 2], a[fm], &bb[fn2][0]);
                    mma_bf16(acc[fm][fn2 * 2 + 1], a[fm], &bb[fn2][2]);
                }
        }
        __syncthreads();
    }

    // ---- epilogue: BN fold + relu + bf16 store
#pragma unroll
    for (int fm = 0; fm < 2; fm++) {
#pragma unroll
        for (int fn = 0; fn < 4; fn++) {
            int r = bm + wm * 32 + fm * 16 + g;
            int c = wn * 32 + fn * 8 + tg * 2;
            float s0 = scale[c], s1 = scale[c + 1];
            float t0 = shift[c], t1 = shift[c + 1];
            float v0 = acc[fm][fn][0] * s0 + t0;
            float v1 = acc[fm][fn][1] * s1 + t1;
            float v2 = acc[fm][fn][2] * s0 + t0;
            float v3 = acc[fm][fn][3] * s1 + t1;
            if (relu) {
                v0 = fmaxf(v0, 0.f); v1 = fmaxf(v1, 0.f);
                v2 = fmaxf(v2, 0.f); v3 = fmaxf(v3, 0.f);
            }
            if (r < NN) {
                bf162 p = __floats2bfloat162_rn(v0, v1);
                *(bf162*)(hout + (size_t)r * DF + c) = p;
            }
            if (r + 8 < NN) {
                bf162 p = __floats2bfloat162_rn(v2, v3);
                *(bf162*)(hout + (size_t)(r + 8) * DF + c) = p;
            }
        }
    }
}

// ---------------- small bf16 GEMM for head: C[M,N] = A[M,K] @ B[N,K]^T ---------
#define SMS 40
__global__ void k_gemm(const bf16* __restrict__ A, const bf16* __restrict__ B,
                       const float* __restrict__ bias, bf16* __restrict__ C,
                       int M, int K, int Nt, int relu) {
    __shared__ __align__(16) bf16 As[128 * SMS];
    __shared__ __align__(16) bf16 Bs[128 * SMS];

    int tid = threadIdx.x;
    int wid = tid >> 5;
    int lane = tid & 31;
    int wm = wid & 3;
    int wn = wid >> 2;
    int g = lane >> 2;
    int tg = lane & 3;
    int bm = blockIdx.x * 128;
    int nb = blockIdx.y * 128;

    uint32_t sAs = (uint32_t)__cvta_generic_to_shared(As);
    uint32_t sBs = (uint32_t)__cvta_generic_to_shared(Bs);

    float acc[2][8][4];
#pragma unroll
    for (int i = 0; i < 2; i++)
#pragma unroll
        for (int j = 0; j < 8; j++)
#pragma unroll
            for (int k = 0; k < 4; k++) acc[i][j][k] = 0.f;

    uint32_t aA = sAs + (uint32_t)(((wm * 32 + (lane & 15)) * SMS + ((lane >> 4) << 3)) * 2);
    uint32_t aB = sBs + (uint32_t)(((wn * 64 + (lane & 7) + ((lane >> 4) & 1) * 8) * SMS +
                                    (((lane >> 3) & 1) << 3)) * 2);

    for (int kt = 0; kt < K; kt += 32) {
#pragma unroll
        for (int i = 0; i < 2; i++) {
            int id = tid + i * 256;
            int row = id >> 2, seg = id & 3;
            int gr = bm + row;
            uint4 v = make_uint4(0, 0, 0, 0);
            if (gr < M) v = *(const uint4*)(A + (size_t)gr * K + kt + seg * 8);
            *(uint4*)(As + row * SMS + seg * 8) = v;
        }
#pragma unroll
        for (int i = 0; i < 2; i++) {
            int id = tid + i * 256;
            int row = id >> 2, seg = id & 3;
            uint4 v = *(const uint4*)(B + (size_t)(nb + row) * K + kt + seg * 8);
            *(uint4*)(Bs + row * SMS + seg * 8) = v;
        }
        __syncthreads();

#pragma unroll
        for (int ks = 0; ks < 2; ks++) {
            int kk = ks * 16;
            unsigned a[2][4], b[4][4];
#pragma unroll
            for (int fm = 0; fm < 2; fm++)
                ldm_x4(a[fm], aA + (uint32_t)((fm * 16 * SMS + kk) * 2));
#pragma unroll
            for (int fn2 = 0; fn2 < 4; fn2++)
                ldm_x4(b[fn2], aB + (uint32_t)((fn2 * 16 * SMS + kk) * 2));
#pragma unroll
            for (int fm = 0; fm < 2; fm++)
#pragma unroll
                for (int fn2 = 0; fn2 < 4; fn2++) {
                    mma_bf16(acc[fm][fn2 * 2], a[fm], &b[fn2][0]);
                    mma_bf16(acc[fm][fn2 * 2 + 1], a[fm], &b[fn2][2]);
                }
        }
        __syncthreads();
    }

#pragma unroll
    for (int fm = 0; fm < 2; fm++) {
#pragma unroll
        for (int fn = 0; fn < 8; fn++) {
            int r = bm + wm * 32 + fm * 16 + g;
            int c = nb + wn * 64 + fn * 8 + tg * 2;
            float t0 = bias[c], t1 = bias[c + 1];
            float v0 = acc[fm][fn][0] + t0;
            float v1 = acc[fm][fn][1] + t1;
            float v2 = acc[fm][fn][2] + t0;
            float v3 = acc[fm][fn][3] + t1;
            if (relu) {
                v0 = fmaxf(v0, 0.f); v1 = fmaxf(v1, 0.f);
                v2 = fmaxf(v2, 0.f); v3 = fmaxf(v3, 0.f);
            }
            if (r < M) {
                bf162 p = __floats2bfloat162_rn(v0, v1);
                *(bf162*)(C + (size_t)r * Nt + c) = p;
            }
            if (r + 8 < M) {
                bf162 p = __floats2bfloat162_rn(v2, v3);
                *(bf162*)(C + (size_t)(r + 8) * Nt + c) = p;
            }
        }
    }
}

// ---------------- head --------------------------------------------------------
__global__ void k_gather(const bf16* __restrict__ h, const int* __restrict__ home,
                         const int* __restrict__ away) {
    int b = (blockIdx.x * blockDim.x + threadIdx.x) >> 5;
    int lane = threadIdx.x & 31;
    if (b >= NBATCH) return;
    const uint2* h2 = (const uint2*)h;
    uint2 hv = h2[(size_t)home[b] * 32 + lane];
    uint2 av = h2[(size_t)away[b] * 32 + lane];
    uint2* G2 = (uint2*)g_G;
    G2[(size_t)b * 64 + lane] = hv;
    G2[(size_t)b * 64 + 32 + lane] = av;
}

__global__ void k_head(const float* __restrict__ fc2w, const float* __restrict__ fc2b,
                       float* __restrict__ out) {
    int b = (blockIdx.x * blockDim.x + threadIdx.x) >> 5;
    int lane = threadIdx.x & 31;
    if (b >= NBATCH) return;
    const uint2* g2 = (const uint2*)g_G2;
    uint2 u = g2[(size_t)b * 32 + lane];
    float2 f0 = __bfloat1622float2(*(bf162*)&u.x);
    float2 f1 = __bfloat1622float2(*(bf162*)&u.y);
    const float4* w4 = (const float4*)fc2w;
    float l[3];
#pragma unroll
    for (int c = 0; c < 3; c++) {
        float4 w = w4[c * 32 + lane];
        float d = f0.x * w.x + f0.y * w.y + f1.x * w.z + f1.y * w.w;
#pragma unroll
        for (int off = 16; off; off >>= 1) d += __shfl_xor_sync(0xffffffffu, d, off);
        l[c] = d + fc2b[c];
    }
    float m = fmaxf(l[0], fmaxf(l[1], l[2]));
    float s = expf(l[0] - m) + expf(l[1] - m) + expf(l[2] - m);
    float ls = m + logf(s);
    if (lane < 3) out[b * 3 + lane] = l[lane] - ls;
}

// ---------------- driver --------------------------------------------------------
extern "C" void kernel_launch(void* const* d_in, const int* in_sizes, int n_in,
                              void* d_out, int out_size) {
    const int* x = (const int*)d_in[0];
    const int* ei = (const int*)d_in[1];
    const int* et = (const int*)d_in[2];
    const int* home = (const int*)d_in[3];
    const int* away = (const int*)d_in[4];
    const float* embed = (const float*)d_in[5];
    const float* rel_w = (const float*)d_in[6];
    const float* root_w = (const float*)d_in[7];
    const float* conv_b = (const float*)d_in[8];
    const float* bn_g = (const float*)d_in[9];
    const float* bn_b = (const float*)d_in[10];
    const float* bn_m = (const float*)d_in[11];
    const float* bn_v = (const float*)d_in[12];
    const float* fc0w = (const float*)d_in[13];
    const float* fc0b = (const float*)d_in[14];
    const float* fc1w = (const float*)d_in[15];
    const float* fc1b = (const float*)d_in[16];
    const float* fc2w = (const float*)d_in[17];
    const float* fc2b = (const float*)d_in[18];
    float* out = (float*)d_out;

    bf16 *p_h, *p_W, *p_W0, *p_W1, *p_G, *p_G1, *p_G2;
    float *p_scale, *p_shift;
    cudaGetSymbolAddress((void**)&p_h, g_hb);
    cudaGetSymbolAddress((void**)&p_W, g_W);
    cudaGetSymbolAddress((void**)&p_scale, g_scale);
    cudaGetSymbolAddress((void**)&p_shift, g_shift);
    cudaGetSymbolAddress((void**)&p_W0, g_W0);
    cudaGetSymbolAddress((void**)&p_W1, g_W1);
    cudaGetSymbolAddress((void**)&p_G, g_G);
    cudaGetSymbolAddress((void**)&p_G1, g_G1);
    cudaGetSymbolAddress((void**)&p_G2, g_G2);

    cudaFuncSetAttribute(k_layer, cudaFuncAttributeMaxDynamicSharedMemorySize,
                         LAYER_SMEM);

    // graph build: bucket CSR over (node, relation)
    k_zero<<<NB2, 256>>>();
    k_hist<<<(NE + 255) / 256, 256>>>(ei, et);
    k2_scanA<<<NB2, 256>>>();
    k2_scanB<<<1, 1024>>>();
    k2_scanC<<<NB2, 256>>>();
    k_scatter<<<(NE + 255) / 256, 256>>>(ei, et);

    // parameter prep
    k_prep_w<<<(3 * KAGG * DF + 255) / 256, 256>>>(rel_w, root_w);
    k_prep_bn<<<2, 256>>>(conv_b, bn_g, bn_b, bn_m, bn_v);
    k_prep_fc<<<(256 * 256 + 128 * 256 + 255) / 256, 256>>>(fc0w, fc1w);
    k_embed<<<(NN * 32 + 255) / 256, 256>>>(x, embed);

    // 3 fused RGCN layers
    bf16* hcur = p_h;
    bf16* hnxt = p_h + (size_t)NN * DF;
    for (int l = 0; l < 3; l++) {
        k_layer<<<(NN + 127) / 128, 512, LAYER_SMEM>>>(
            hcur, p_W + (size_t)l * KAGG * DF, p_scale + l * DF, p_shift + l * DF,
            hnxt, (l < 2) ? 1 : 0);
        bf16* tmp = hcur; hcur = hnxt; hnxt = tmp;
    }

    // head MLP
    k_gather<<<(NBATCH * 32 + 255) / 256, 256>>>(hcur, home, away);
    k_gemm<<<dim3(NBATCH / 128, 2), 256>>>(p_G, p_W0, fc0b, p_G1, NBATCH, 256, 256, 1);
    k_gemm<<<dim3(NBATCH / 128, 1), 256>>>(p_G1, p_W1, fc1b, p_G2, NBATCH, 256, 128, 1);
    k_head<<<(NBATCH * 32 + 255) / 256, 256>>>(fc2w, fc2b, out);
}